// round 12
// baseline (speedup 1.0000x reference)
#include <cuda_runtime.h>
#include <cuda_pipeline.h>
#include <cuda_fp16.h>
#include <mma.h>
#include <math.h>
#include <stdint.h>

using namespace nvcuda;

// ---------------------------------------------------------------------------
// SwinTransformerBlock  (B=32, H=W=56, C=256, G=256, WIN=7, SHIFT=3, HEADS=8)
// Round 11: R10 GEMMs + WMMA tensor-core attention (49->64 padded tiles).
// ---------------------------------------------------------------------------

#define BB      32
#define HH      56
#define CC      256
#define GG      256
#define CGDIM   512
#define NHEADS  8
#define NTOK    49
#define TOK     (BB*HH*HH)
#define MLPH    1024
#define QSCALE  0.17677669529663687f
#define EPSV    1e-5f

#define AS_LD   40
#define BS_LD   136
#define ASTG    (128*AS_LD)
#define BSTG    (32*BS_LD)
#define SMEM_SZ ((3*ASTG + 3*BSTG)*2 + 8*16*20*4)

// ------------------------- scratch (device globals) ------------------------
__device__ __half g_Wqk[CGDIM*CGDIM];        // [K=512][N=512] q|k
__device__ __half g_Wv [CC*CC];              // [K=256][N=256] v
__device__ float  g_bc [768];
__device__ __half g_Wp [CC*CC];
__device__ __half g_Wf1[CC*MLPH];
__device__ __half g_Wf2[MLPH*CC];
__device__ __half g_win[(size_t)TOK*CGDIM];
__device__ __half g_qkv[(size_t)TOK*768];
__device__ __half g_att[(size_t)TOK*CC];
__device__ float  g_y1 [(size_t)TOK*CC];
__device__ __half g_ln2[(size_t)TOK*CC];
__device__ __half g_hid[(size_t)TOK*MLPH];

__device__ __forceinline__ int tok_map(int t) {
    int gw = t / NTOK;
    int n  = t - gw * NTOK;
    int b  = gw >> 6;
    int w  = gw & 63;
    int r  = (w >> 3) * 7 + n / 7;
    int c  = (w & 7) * 7 + n % 7;
    int sr = r + 3; if (sr >= HH) sr -= HH;
    int sc = c + 3; if (sc >= HH) sc -= HH;
    return (b * HH + sr) * HH + sc;
}

// ------------------- kernel 0: build qk / v weights + biases ----------------
__global__ void build_w_kernel(const float* __restrict__ qw, const float* __restrict__ qb,
                               const float* __restrict__ kw, const float* __restrict__ kb,
                               const float* __restrict__ vw, const float* __restrict__ vb) {
    int i = blockIdx.x * blockDim.x + threadIdx.x;
    if (i < CGDIM * CGDIM) {
        int k = i >> 9, n = i & 511;
        g_Wqk[i] = __float2half_rn((n < 256) ? qw[k * 256 + n] : kw[k * 256 + (n - 256)]);
    }
    if (i < CC * CC) {
        int k = i >> 8, n = i & 255;
        g_Wv[i] = __float2half_rn(vw[k * 256 + n]);
    }
    if (i < 768)
        g_bc[i] = (i < 256) ? qb[i] : ((i < 512) ? kb[i - 256] : vb[i - 512]);
}

// -------------------- convert proj / fc1 / fc2 weights to half --------------
__global__ void round_w_kernel(const float* __restrict__ pw,
                               const float* __restrict__ f1w,
                               const float* __restrict__ f2w) {
    int i = blockIdx.x * blockDim.x + threadIdx.x;
    if (i < CC*CC)   g_Wp[i]  = __float2half_rn(pw[i]);
    if (i < CC*MLPH) { g_Wf1[i] = __float2half_rn(f1w[i]); g_Wf2[i] = __float2half_rn(f2w[i]); }
}

// ------ kernel 1: LN1 + roll + window partition + concat (warp per row) -----
__global__ void __launch_bounds__(256)
prep_kernel(const float* __restrict__ x, const float* __restrict__ guid,
            const float* __restrict__ w, const float* __restrict__ b) {
    int warp = threadIdx.x >> 5, lane = threadIdx.x & 31;
    int row = blockIdx.x * 8 + warp;          // window-major token
    int src = tok_map(row);
    int c0  = lane * 8;
    const float* xr = x + (size_t)src * CC;
    float4 v0 = *(const float4*)(xr + c0);
    float4 v1 = *(const float4*)(xr + c0 + 4);
    float sum = v0.x + v0.y + v0.z + v0.w + v1.x + v1.y + v1.z + v1.w;
    float sq  = v0.x*v0.x + v0.y*v0.y + v0.z*v0.z + v0.w*v0.w
              + v1.x*v1.x + v1.y*v1.y + v1.z*v1.z + v1.w*v1.w;
    #pragma unroll
    for (int o = 16; o > 0; o >>= 1) {
        sum += __shfl_xor_sync(0xffffffffu, sum, o);
        sq  += __shfl_xor_sync(0xffffffffu, sq,  o);
    }
    float mu = sum * (1.f / CC);
    float rs = rsqrtf(sq * (1.f / CC) - mu * mu + EPSV);
    float4 w0 = *(const float4*)(w + c0), w1 = *(const float4*)(w + c0 + 4);
    float4 b0 = *(const float4*)(b + c0), b1 = *(const float4*)(b + c0 + 4);
    __half2 h[4];
    h[0] = __floats2half2_rn((v0.x-mu)*rs*w0.x+b0.x, (v0.y-mu)*rs*w0.y+b0.y);
    h[1] = __floats2half2_rn((v0.z-mu)*rs*w0.z+b0.z, (v0.w-mu)*rs*w0.w+b0.w);
    h[2] = __floats2half2_rn((v1.x-mu)*rs*w1.x+b1.x, (v1.y-mu)*rs*w1.y+b1.y);
    h[3] = __floats2half2_rn((v1.z-mu)*rs*w1.z+b1.z, (v1.w-mu)*rs*w1.w+b1.w);
    *(uint4*)&g_win[(size_t)row * CGDIM + c0] = *(uint4*)h;
    const float* gr = guid + (size_t)src * GG;
    float4 g0 = *(const float4*)(gr + c0), g1 = *(const float4*)(gr + c0 + 4);
    h[0] = __floats2half2_rn(g0.x, g0.y);
    h[1] = __floats2half2_rn(g0.z, g0.w);
    h[2] = __floats2half2_rn(g1.x, g1.y);
    h[3] = __floats2half2_rn(g1.z, g1.w);
    *(uint4*)&g_win[(size_t)row * CGDIM + CC + c0] = *(uint4*)h;
}

// --------------------- LayerNorm (warp per row, half out) -------------------
__global__ void __launch_bounds__(256)
ln_kernel(const float* __restrict__ in, const float* __restrict__ w,
          const float* __restrict__ b, __half* __restrict__ out) {
    int warp = threadIdx.x >> 5, lane = threadIdx.x & 31;
    int row = blockIdx.x * 8 + warp;
    int c0  = lane * 8;
    const float* xr = in + (size_t)row * CC;
    float4 v0 = *(const float4*)(xr + c0);
    float4 v1 = *(const float4*)(xr + c0 + 4);
    float sum = v0.x + v0.y + v0.z + v0.w + v1.x + v1.y + v1.z + v1.w;
    float sq  = v0.x*v0.x + v0.y*v0.y + v0.z*v0.z + v0.w*v0.w
              + v1.x*v1.x + v1.y*v1.y + v1.z*v1.z + v1.w*v1.w;
    #pragma unroll
    for (int o = 16; o > 0; o >>= 1) {
        sum += __shfl_xor_sync(0xffffffffu, sum, o);
        sq  += __shfl_xor_sync(0xffffffffu, sq,  o);
    }
    float mu = sum * (1.f / CC);
    float rs = rsqrtf(sq * (1.f / CC) - mu * mu + EPSV);
    float4 w0 = *(const float4*)(w + c0), w1 = *(const float4*)(w + c0 + 4);
    float4 b0 = *(const float4*)(b + c0), b1 = *(const float4*)(b + c0 + 4);
    __half2 h[4];
    h[0] = __floats2half2_rn((v0.x-mu)*rs*w0.x+b0.x, (v0.y-mu)*rs*w0.y+b0.y);
    h[1] = __floats2half2_rn((v0.z-mu)*rs*w0.z+b0.z, (v0.w-mu)*rs*w0.w+b0.w);
    h[2] = __floats2half2_rn((v1.x-mu)*rs*w1.x+b1.x, (v1.y-mu)*rs*w1.y+b1.y);
    h[3] = __floats2half2_rn((v1.z-mu)*rs*w1.z+b1.z, (v1.w-mu)*rs*w1.w+b1.w);
    *(uint4*)&out[(size_t)row * CC + c0] = *(uint4*)h;
}

// ------------------ stage loader: 128x32 A + 32x128 B (half) ----------------
__device__ __forceinline__ void stage_load(__half* Asd, __half* Bsd,
                                           const __half* __restrict__ A, int lda,
                                           const __half* __restrict__ W, int ldb,
                                           int m0, int n0, int k0, int tid) {
    #pragma unroll
    for (int r = 0; r < 2; r++) {
        int id  = tid + r * 256;
        int row = id >> 2, kq = (id & 3) << 3;     // 128 rows x 32 halves
        __pipeline_memcpy_async(Asd + row * AS_LD + kq,
                                A + (size_t)(m0 + row) * lda + k0 + kq, 16);
    }
    #pragma unroll
    for (int r = 0; r < 2; r++) {
        int id   = tid + r * 256;
        int krow = id >> 4, nq = (id & 15) << 3;   // 32 rows x 128 halves
        __pipeline_memcpy_async(Bsd + krow * BS_LD + nq,
                                W + (size_t)(k0 + krow) * ldb + n0 + nq, 16);
    }
}

// --- fp16 WMMA GEMM: 128x128x32 CTA, 8 warps, 64x32/warp tile, 2 CTA/SM -----
// MODE 0: C(half)  = A@W + bias                  (qkv)
// MODE 1: C(float)[map(m)] = res[map(m)] + A@W + bias   (proj+reverse+residual)
// MODE 2: C(half)  = gelu(A@W + bias)            (fc1)
// MODE 3: C(float) = res + A@W + bias            (fc2+residual)
template <int MODE>
__global__ void __launch_bounds__(256, 2)
wgemm_kernel(const __half* __restrict__ A, int lda,
             const __half* __restrict__ W, int ldb,
             const float* __restrict__ bias, const float* __restrict__ res,
             void* __restrict__ Cv, int ldc, int K) {
    extern __shared__ __half smh[];
    __half* As = smh;                        // 3 stages of 128 x AS_LD
    __half* Bs = smh + 3 * ASTG;             // 3 stages of 32  x BS_LD
    float*  wb = (float*)(Bs + 3 * BSTG);    // 8 warps x 16 x 20

    int tid  = threadIdx.x;
    int warp = tid >> 5, lane = tid & 31;
    int wm = warp >> 2;                      // 0..1 -> 64-row slab
    int wn = warp & 3;                       // 0..3 -> 32-col slab
    int m0 = blockIdx.y * 128;
    int n0 = blockIdx.x * 128;

    wmma::fragment<wmma::accumulator, 16, 16, 16, float> acc[4][2];
    #pragma unroll
    for (int i = 0; i < 4; i++)
        #pragma unroll
        for (int j = 0; j < 2; j++) wmma::fill_fragment(acc[i][j], 0.f);

    const int KT = K >> 5;

    stage_load(As, Bs, A, lda, W, ldb, m0, n0, 0, tid);
    __pipeline_commit();
    stage_load(As + ASTG, Bs + BSTG, A, lda, W, ldb, m0, n0, 32, tid);
    __pipeline_commit();

    for (int kt = 0; kt < KT; kt++) {
        __pipeline_wait_prior(1);            // stage kt arrived
        __syncthreads();                     // all warps done with stage kt-1
        if (kt + 2 < KT) {
            int st = (kt + 2) % 3;
            stage_load(As + st * ASTG, Bs + st * BSTG, A, lda, W, ldb,
                       m0, n0, (kt + 2) << 5, tid);
        }
        __pipeline_commit();

        int cur = kt % 3;
        const __half* Ac = As + cur * ASTG + wm * 64 * AS_LD;
        const __half* Bc = Bs + cur * BSTG + wn * 32;
        #pragma unroll
        for (int ks = 0; ks < 2; ks++) {
            wmma::fragment<wmma::matrix_b, 16, 16, 16, __half, wmma::row_major> bf[2];
            #pragma unroll
            for (int j = 0; j < 2; j++)
                wmma::load_matrix_sync(bf[j], Bc + ks * 16 * BS_LD + j * 16, BS_LD);
            #pragma unroll
            for (int i = 0; i < 4; i++) {
                wmma::fragment<wmma::matrix_a, 16, 16, 16, __half, wmma::row_major> af;
                wmma::load_matrix_sync(af, Ac + i * 16 * AS_LD + ks * 16, AS_LD);
                wmma::mma_sync(acc[i][0], af, bf[0], acc[i][0]);
                wmma::mma_sync(acc[i][1], af, bf[1], acc[i][1]);
            }
        }
    }
    __syncthreads();

    // ------------------------------ epilogue --------------------------------
    int er = lane >> 1, ec = (lane & 1) << 3;
    float* wwb = wb + warp * 16 * 20;
    #pragma unroll
    for (int i = 0; i < 4; i++) {
        int gm   = m0 + wm * 64 + i * 16 + er;
        int orow = (MODE == 1) ? tok_map(gm) : gm;
        size_t rowbase = (size_t)orow * ldc;
        #pragma unroll
        for (int j = 0; j < 2; j++) {
            wmma::store_matrix_sync(wwb, acc[i][j], 20, wmma::mem_row_major);
            __syncwarp();
            int gn = n0 + wn * 32 + j * 16 + ec;
            const float* src = wwb + er * 20 + ec;
            float4 v0 = *(const float4*)(src);
            float4 v1 = *(const float4*)(src + 4);
            float4 b0 = *(const float4*)&bias[gn];
            float4 b1 = *(const float4*)&bias[gn + 4];
            float o[8] = {v0.x + b0.x, v0.y + b0.y, v0.z + b0.z, v0.w + b0.w,
                          v1.x + b1.x, v1.y + b1.y, v1.z + b1.z, v1.w + b1.w};
            if (MODE == 2) {
                #pragma unroll
                for (int e = 0; e < 8; e++)
                    o[e] = 0.5f * o[e] * (1.f + erff(o[e] * 0.70710678118654752f));
            }
            if (MODE == 0 || MODE == 2) {
                __half* Ch = (__half*)Cv;
                __half2* dst = (__half2*)&Ch[rowbase + gn];
                dst[0] = __floats2half2_rn(o[0], o[1]);
                dst[1] = __floats2half2_rn(o[2], o[3]);
                dst[2] = __floats2half2_rn(o[4], o[5]);
                dst[3] = __floats2half2_rn(o[6], o[7]);
            } else {
                float4 r0 = *(const float4*)&res[rowbase + gn];
                float4 r1 = *(const float4*)&res[rowbase + gn + 4];
                o[0] += r0.x; o[1] += r0.y; o[2] += r0.z; o[3] += r0.w;
                o[4] += r1.x; o[5] += r1.y; o[6] += r1.z; o[7] += r1.w;
                float* Cf = (float*)Cv;
                *(float4*)&Cf[rowbase + gn]     = make_float4(o[0], o[1], o[2], o[3]);
                *(float4*)&Cf[rowbase + gn + 4] = make_float4(o[4], o[5], o[6], o[7]);
            }
            __syncwarp();
        }
    }
}

// ---------- attention via WMMA: one block per (window, head), 64-pad --------
#define QK_LD 40
#define S_LD  68
#define P_LD  72
__global__ void __launch_bounds__(256)
attn_kernel(const __half* __restrict__ qkv, __half* __restrict__ out) {
    int blk  = blockIdx.x;
    int gw   = blk >> 3;
    int head = blk & 7;
    int w    = gw & 63;
    int tid  = threadIdx.x;
    int warp = tid >> 5, lane = tid & 31;

    __shared__ __half qs[64 * QK_LD], ks[64 * QK_LD], vs[64 * QK_LD];
    __shared__ float  Sf[64 * S_LD];
    __shared__ __half pb[64 * P_LD];
    __shared__ int    lab[NTOK];

    if (tid < NTOK) {
        int r = (w >> 3) * 7 + tid / 7;
        int c = (w & 7) * 7 + tid % 7;
        int rr = (r < 49) ? 0 : ((r < 53) ? 1 : 2);
        int cr = (c < 49) ? 0 : ((c < 53) ? 1 : 2);
        lab[tid] = rr * 3 + cr;
    }
    // zero P (pad rows/cols must be exact zeros for the AV GEMM)
    for (int idx = tid; idx < 64 * 9; idx += 256)
        ((uint4*)pb)[idx] = make_uint4(0, 0, 0, 0);

    // load q/k/v (rows >= 49 zeroed; garbage could be NaN and 0*NaN = NaN)
    const __half* base = qkv + (size_t)gw * NTOK * 768 + head * 32;
    {
        int n = tid >> 2, i = tid & 3;               // 64 rows x 4 uint4
        uint4 zq = make_uint4(0,0,0,0), zk = zq, zv = zq;
        if (n < NTOK) {
            const uint4* b4 = (const uint4*)(base + n * 768);
            zq = b4[i]; zk = b4[32 + i]; zv = b4[64 + i];
        }
        *(uint4*)&qs[n * QK_LD + i * 8] = zq;
        *(uint4*)&ks[n * QK_LD + i * 8] = zk;
        *(uint4*)&vs[n * QK_LD + i * 8] = zv;
    }
    __syncthreads();

    // S = q @ k^T : 4x4 tiles of 16x16, 2 tiles per warp, K=32
    #pragma unroll
    for (int t2 = 0; t2 < 2; t2++) {
        int t = warp * 2 + t2;
        int ti = t >> 2, tj = t & 3;
        wmma::fragment<wmma::accumulator, 16, 16, 16, float> sacc;
        wmma::fill_fragment(sacc, 0.f);
        #pragma unroll
        for (int kk = 0; kk < 32; kk += 16) {
            wmma::fragment<wmma::matrix_a, 16, 16, 16, __half, wmma::row_major> af;
            wmma::fragment<wmma::matrix_b, 16, 16, 16, __half, wmma::col_major> bf;
            wmma::load_matrix_sync(af, qs + ti * 16 * QK_LD + kk, QK_LD);
            wmma::load_matrix_sync(bf, ks + tj * 16 * QK_LD + kk, QK_LD);
            wmma::mma_sync(sacc, af, bf, sacc);
        }
        wmma::store_matrix_sync(Sf + ti * 16 * S_LD + tj * 16, sacc, S_LD,
                                wmma::mem_row_major);
    }
    __syncthreads();

    // softmax rows 0..48 (warp per row), write half P
    for (int n = warp; n < NTOK; n += 8) {
        int l0 = lab[n];
        float s0 = (lane < NTOK)
                 ? Sf[n * S_LD + lane] * QSCALE + ((l0 == lab[lane]) ? 0.f : -100.f)
                 : -1e30f;
        float s1 = (lane + 32 < NTOK)
                 ? Sf[n * S_LD + lane + 32] * QSCALE + ((l0 == lab[lane + 32]) ? 0.f : -100.f)
                 : -1e30f;
        float mx = fmaxf(s0, s1);
        #pragma unroll
        for (int o = 16; o > 0; o >>= 1) mx = fmaxf(mx, __shfl_xor_sync(0xffffffffu, mx, o));
        float e0 = (lane      < NTOK) ? __expf(s0 - mx) : 0.f;
        float e1 = (lane + 32 < NTOK) ? __expf(s1 - mx) : 0.f;
        float sm = e0 + e1;
        #pragma unroll
        for (int o = 16; o > 0; o >>= 1) sm += __shfl_xor_sync(0xffffffffu, sm, o);
        float inv = 1.f / sm;
        if (lane      < NTOK) pb[n * P_LD + lane]      = __float2half_rn(e0 * inv);
        if (lane + 32 < NTOK) pb[n * P_LD + lane + 32] = __float2half_rn(e1 * inv);
    }
    __syncthreads();

    // O = P @ V : 4x2 tiles of 16x16, 1 tile per warp, K=64
    {
        int ti = warp >> 1, tj = warp & 1;
        wmma::fragment<wmma::accumulator, 16, 16, 16, float> oacc;
        wmma::fill_fragment(oacc, 0.f);
        #pragma unroll
        for (int kk = 0; kk < 64; kk += 16) {
            wmma::fragment<wmma::matrix_a, 16, 16, 16, __half, wmma::row_major> af;
            wmma::fragment<wmma::matrix_b, 16, 16, 16, __half, wmma::row_major> bf;
            wmma::load_matrix_sync(af, pb + ti * 16 * P_LD + kk, P_LD);
            wmma::load_matrix_sync(bf, vs + kk * QK_LD + tj * 16, QK_LD);
            wmma::mma_sync(oacc, af, bf, oacc);
        }
        wmma::store_matrix_sync(Sf + ti * 16 * S_LD + tj * 16, oacc, S_LD,
                                wmma::mem_row_major);
    }
    __syncthreads();

    // write rows 0..48 (32 halves each)
    if (tid < NTOK * 4) {
        int n = tid >> 2, q = tid & 3;
        const float* src = Sf + n * S_LD + q * 8;
        __half2 h[4];
        h[0] = __floats2half2_rn(src[0], src[1]);
        h[1] = __floats2half2_rn(src[2], src[3]);
        h[2] = __floats2half2_rn(src[4], src[5]);
        h[3] = __floats2half2_rn(src[6], src[7]);
        *(uint4*)&out[((size_t)gw * NTOK + n) * CC + head * 32 + q * 8] = *(uint4*)h;
    }
}

// --------------------------------- launch -----------------------------------
extern "C" void kernel_launch(void* const* d_in, const int* in_sizes, int n_in,
                              void* d_out, int out_size) {
    const float* x   = (const float*)d_in[0];
    const float* ag  = (const float*)d_in[1];
    const float* n1w = (const float*)d_in[2];
    const float* n1b = (const float*)d_in[3];
    const float* qw  = (const float*)d_in[4];
    const float* qb  = (const float*)d_in[5];
    const float* kw  = (const float*)d_in[6];
    const float* kb  = (const float*)d_in[7];
    const float* vw  = (const float*)d_in[8];
    const float* vb  = (const float*)d_in[9];
    const float* pw  = (const float*)d_in[10];
    const float* pb_ = (const float*)d_in[11];
    const float* n2w = (const float*)d_in[12];
    const float* n2b = (const float*)d_in[13];
    const float* f1w = (const float*)d_in[14];
    const float* f1b = (const float*)d_in[15];
    const float* f2w = (const float*)d_in[16];
    const float* f2b = (const float*)d_in[17];
    float* out = (float*)d_out;

    __half *p_wqk, *p_wv, *p_wp, *p_wf1, *p_wf2, *p_win, *p_qkv, *p_att, *p_ln2, *p_hid;
    float  *p_bc, *p_y1;
    cudaGetSymbolAddress((void**)&p_wqk, g_Wqk);
    cudaGetSymbolAddress((void**)&p_wv,  g_Wv);
    cudaGetSymbolAddress((void**)&p_bc,  g_bc);
    cudaGetSymbolAddress((void**)&p_wp,  g_Wp);
    cudaGetSymbolAddress((void**)&p_wf1, g_Wf1);
    cudaGetSymbolAddress((void**)&p_wf2, g_Wf2);
    cudaGetSymbolAddress((void**)&p_win, g_win);
    cudaGetSymbolAddress((void**)&p_qkv, g_qkv);
    cudaGetSymbolAddress((void**)&p_att, g_att);
    cudaGetSymbolAddress((void**)&p_y1,  g_y1);
    cudaGetSymbolAddress((void**)&p_ln2, g_ln2);
    cudaGetSymbolAddress((void**)&p_hid, g_hid);

    cudaFuncSetAttribute(wgemm_kernel<0>, cudaFuncAttributeMaxDynamicSharedMemorySize, SMEM_SZ);
    cudaFuncSetAttribute(wgemm_kernel<1>, cudaFuncAttributeMaxDynamicSharedMemorySize, SMEM_SZ);
    cudaFuncSetAttribute(wgemm_kernel<2>, cudaFuncAttributeMaxDynamicSharedMemorySize, SMEM_SZ);
    cudaFuncSetAttribute(wgemm_kernel<3>, cudaFuncAttributeMaxDynamicSharedMemorySize, SMEM_SZ);

    const int MT = TOK / 128;   // 784 M-tiles

    build_w_kernel<<<(CGDIM * CGDIM + 255) / 256, 256>>>(qw, qb, kw, kb, vw, vb);
    round_w_kernel<<<(CC * MLPH + 255) / 256, 256>>>(pw, f1w, f2w);
    prep_kernel<<<TOK / 8, 256>>>(x, ag, n1w, n1b);
    // q,k : [TOK,512] @ [512,512] -> qkv cols 0..511 (half out)
    wgemm_kernel<0><<<dim3(4, MT), 256, SMEM_SZ>>>(p_win, CGDIM, p_wqk, CGDIM,
                                                   p_bc, nullptr, p_qkv, 768, 512);
    // v   : [TOK,256] @ [256,256] -> qkv cols 512..767
    wgemm_kernel<0><<<dim3(2, MT), 256, SMEM_SZ>>>(p_win, CGDIM, p_wv, CC,
                                                   p_bc + 512, nullptr, p_qkv + 512, 768, 256);
    attn_kernel<<<(TOK / NTOK) * NHEADS, 256>>>(p_qkv, p_att);
    wgemm_kernel<1><<<dim3(2, MT), 256, SMEM_SZ>>>(p_att, CC, p_wp, CC,
                                                   pb_, x, p_y1, CC, 256);
    ln_kernel<<<TOK / 8, 256>>>(p_y1, n2w, n2b, p_ln2);
    wgemm_kernel<2><<<dim3(8, MT), 256, SMEM_SZ>>>(p_ln2, CC, p_wf1, MLPH,
                                                   f1b, nullptr, p_hid, MLPH, 256);
    wgemm_kernel<3><<<dim3(2, MT), 256, SMEM_SZ>>>(p_hid, MLPH, p_wf2, CC,
                                                   f2b, p_y1, out, CC, 1024);
}

// round 13
// speedup vs baseline: 1.3425x; 1.3425x over previous
#include <cuda_runtime.h>
#include <cuda_pipeline.h>
#include <cuda_fp16.h>
#include <mma.h>
#include <math.h>
#include <stdint.h>

using namespace nvcuda;

// ---------------------------------------------------------------------------
// SwinTransformerBlock  (B=32, H=W=56, C=256, G=256, WIN=7, SHIFT=3, HEADS=8)
// Round 12: R10 pipeline (best) + AV 2-row register tiling in attention.
// ---------------------------------------------------------------------------

#define BB      32
#define HH      56
#define CC      256
#define GG      256
#define CGDIM   512
#define NHEADS  8
#define NTOK    49
#define TOK     (BB*HH*HH)
#define MLPH    1024
#define QSCALE  0.17677669529663687f
#define EPSV    1e-5f

#define AS_LD   40
#define BS_LD   136
#define ASTG    (128*AS_LD)
#define BSTG    (32*BS_LD)
#define SMEM_SZ ((3*ASTG + 3*BSTG)*2 + 8*16*20*4)

// ------------------------- scratch (device globals) ------------------------
__device__ __half g_Wqk[CGDIM*CGDIM];        // [K=512][N=512] q|k
__device__ __half g_Wv [CC*CC];              // [K=256][N=256] v
__device__ float  g_bc [768];
__device__ __half g_Wp [CC*CC];
__device__ __half g_Wf1[CC*MLPH];
__device__ __half g_Wf2[MLPH*CC];
__device__ __half g_win[(size_t)TOK*CGDIM];
__device__ __half g_qkv[(size_t)TOK*768];
__device__ __half g_att[(size_t)TOK*CC];
__device__ float  g_y1 [(size_t)TOK*CC];
__device__ __half g_ln2[(size_t)TOK*CC];
__device__ __half g_hid[(size_t)TOK*MLPH];

__device__ __forceinline__ int tok_map(int t) {
    int gw = t / NTOK;
    int n  = t - gw * NTOK;
    int b  = gw >> 6;
    int w  = gw & 63;
    int r  = (w >> 3) * 7 + n / 7;
    int c  = (w & 7) * 7 + n % 7;
    int sr = r + 3; if (sr >= HH) sr -= HH;
    int sc = c + 3; if (sc >= HH) sc -= HH;
    return (b * HH + sr) * HH + sc;
}

__device__ __forceinline__ void cvt8(float* f, uint4 u) {
    __half2* h = (__half2*)&u;
    float2 t;
    t = __half22float2(h[0]); f[0] = t.x; f[1] = t.y;
    t = __half22float2(h[1]); f[2] = t.x; f[3] = t.y;
    t = __half22float2(h[2]); f[4] = t.x; f[5] = t.y;
    t = __half22float2(h[3]); f[6] = t.x; f[7] = t.y;
}

// ------------------- kernel 0: build qk / v weights + biases ----------------
__global__ void build_w_kernel(const float* __restrict__ qw, const float* __restrict__ qb,
                               const float* __restrict__ kw, const float* __restrict__ kb,
                               const float* __restrict__ vw, const float* __restrict__ vb) {
    int i = blockIdx.x * blockDim.x + threadIdx.x;
    if (i < CGDIM * CGDIM) {
        int k = i >> 9, n = i & 511;
        g_Wqk[i] = __float2half_rn((n < 256) ? qw[k * 256 + n] : kw[k * 256 + (n - 256)]);
    }
    if (i < CC * CC) {
        int k = i >> 8, n = i & 255;
        g_Wv[i] = __float2half_rn(vw[k * 256 + n]);
    }
    if (i < 768)
        g_bc[i] = (i < 256) ? qb[i] : ((i < 512) ? kb[i - 256] : vb[i - 512]);
}

// -------------------- convert proj / fc1 / fc2 weights to half --------------
__global__ void round_w_kernel(const float* __restrict__ pw,
                               const float* __restrict__ f1w,
                               const float* __restrict__ f2w) {
    int i = blockIdx.x * blockDim.x + threadIdx.x;
    if (i < CC*CC)   g_Wp[i]  = __float2half_rn(pw[i]);
    if (i < CC*MLPH) { g_Wf1[i] = __float2half_rn(f1w[i]); g_Wf2[i] = __float2half_rn(f2w[i]); }
}

// ------ kernel 1: LN1 + roll + window partition + concat (warp per row) -----
__global__ void __launch_bounds__(256)
prep_kernel(const float* __restrict__ x, const float* __restrict__ guid,
            const float* __restrict__ w, const float* __restrict__ b) {
    int warp = threadIdx.x >> 5, lane = threadIdx.x & 31;
    int row = blockIdx.x * 8 + warp;          // window-major token
    int src = tok_map(row);
    int c0  = lane * 8;
    const float* xr = x + (size_t)src * CC;
    float4 v0 = *(const float4*)(xr + c0);
    float4 v1 = *(const float4*)(xr + c0 + 4);
    float sum = v0.x + v0.y + v0.z + v0.w + v1.x + v1.y + v1.z + v1.w;
    float sq  = v0.x*v0.x + v0.y*v0.y + v0.z*v0.z + v0.w*v0.w
              + v1.x*v1.x + v1.y*v1.y + v1.z*v1.z + v1.w*v1.w;
    #pragma unroll
    for (int o = 16; o > 0; o >>= 1) {
        sum += __shfl_xor_sync(0xffffffffu, sum, o);
        sq  += __shfl_xor_sync(0xffffffffu, sq,  o);
    }
    float mu = sum * (1.f / CC);
    float rs = rsqrtf(sq * (1.f / CC) - mu * mu + EPSV);
    float4 w0 = *(const float4*)(w + c0), w1 = *(const float4*)(w + c0 + 4);
    float4 b0 = *(const float4*)(b + c0), b1 = *(const float4*)(b + c0 + 4);
    __half2 h[4];
    h[0] = __floats2half2_rn((v0.x-mu)*rs*w0.x+b0.x, (v0.y-mu)*rs*w0.y+b0.y);
    h[1] = __floats2half2_rn((v0.z-mu)*rs*w0.z+b0.z, (v0.w-mu)*rs*w0.w+b0.w);
    h[2] = __floats2half2_rn((v1.x-mu)*rs*w1.x+b1.x, (v1.y-mu)*rs*w1.y+b1.y);
    h[3] = __floats2half2_rn((v1.z-mu)*rs*w1.z+b1.z, (v1.w-mu)*rs*w1.w+b1.w);
    *(uint4*)&g_win[(size_t)row * CGDIM + c0] = *(uint4*)h;
    const float* gr = guid + (size_t)src * GG;
    float4 g0 = *(const float4*)(gr + c0), g1 = *(const float4*)(gr + c0 + 4);
    h[0] = __floats2half2_rn(g0.x, g0.y);
    h[1] = __floats2half2_rn(g0.z, g0.w);
    h[2] = __floats2half2_rn(g1.x, g1.y);
    h[3] = __floats2half2_rn(g1.z, g1.w);
    *(uint4*)&g_win[(size_t)row * CGDIM + CC + c0] = *(uint4*)h;
}

// --------------------- LayerNorm (warp per row, half out) -------------------
__global__ void __launch_bounds__(256)
ln_kernel(const float* __restrict__ in, const float* __restrict__ w,
          const float* __restrict__ b, __half* __restrict__ out) {
    int warp = threadIdx.x >> 5, lane = threadIdx.x & 31;
    int row = blockIdx.x * 8 + warp;
    int c0  = lane * 8;
    const float* xr = in + (size_t)row * CC;
    float4 v0 = *(const float4*)(xr + c0);
    float4 v1 = *(const float4*)(xr + c0 + 4);
    float sum = v0.x + v0.y + v0.z + v0.w + v1.x + v1.y + v1.z + v1.w;
    float sq  = v0.x*v0.x + v0.y*v0.y + v0.z*v0.z + v0.w*v0.w
              + v1.x*v1.x + v1.y*v1.y + v1.z*v1.z + v1.w*v1.w;
    #pragma unroll
    for (int o = 16; o > 0; o >>= 1) {
        sum += __shfl_xor_sync(0xffffffffu, sum, o);
        sq  += __shfl_xor_sync(0xffffffffu, sq,  o);
    }
    float mu = sum * (1.f / CC);
    float rs = rsqrtf(sq * (1.f / CC) - mu * mu + EPSV);
    float4 w0 = *(const float4*)(w + c0), w1 = *(const float4*)(w + c0 + 4);
    float4 b0 = *(const float4*)(b + c0), b1 = *(const float4*)(b + c0 + 4);
    __half2 h[4];
    h[0] = __floats2half2_rn((v0.x-mu)*rs*w0.x+b0.x, (v0.y-mu)*rs*w0.y+b0.y);
    h[1] = __floats2half2_rn((v0.z-mu)*rs*w0.z+b0.z, (v0.w-mu)*rs*w0.w+b0.w);
    h[2] = __floats2half2_rn((v1.x-mu)*rs*w1.x+b1.x, (v1.y-mu)*rs*w1.y+b1.y);
    h[3] = __floats2half2_rn((v1.z-mu)*rs*w1.z+b1.z, (v1.w-mu)*rs*w1.w+b1.w);
    *(uint4*)&out[(size_t)row * CC + c0] = *(uint4*)h;
}

// ------------------ stage loader: 128x32 A + 32x128 B (half) ----------------
__device__ __forceinline__ void stage_load(__half* Asd, __half* Bsd,
                                           const __half* __restrict__ A, int lda,
                                           const __half* __restrict__ W, int ldb,
                                           int m0, int n0, int k0, int tid) {
    #pragma unroll
    for (int r = 0; r < 2; r++) {
        int id  = tid + r * 256;
        int row = id >> 2, kq = (id & 3) << 3;     // 128 rows x 32 halves
        __pipeline_memcpy_async(Asd + row * AS_LD + kq,
                                A + (size_t)(m0 + row) * lda + k0 + kq, 16);
    }
    #pragma unroll
    for (int r = 0; r < 2; r++) {
        int id   = tid + r * 256;
        int krow = id >> 4, nq = (id & 15) << 3;   // 32 rows x 128 halves
        __pipeline_memcpy_async(Bsd + krow * BS_LD + nq,
                                W + (size_t)(k0 + krow) * ldb + n0 + nq, 16);
    }
}

// --- fp16 WMMA GEMM: 128x128x32 CTA, 8 warps, 64x32/warp tile, 2 CTA/SM -----
// MODE 0: C(half)  = A@W + bias                  (qkv)
// MODE 1: C(float)[map(m)] = res[map(m)] + A@W + bias   (proj+reverse+residual)
// MODE 2: C(half)  = gelu(A@W + bias)            (fc1)
// MODE 3: C(float) = res + A@W + bias            (fc2+residual)
template <int MODE>
__global__ void __launch_bounds__(256, 2)
wgemm_kernel(const __half* __restrict__ A, int lda,
             const __half* __restrict__ W, int ldb,
             const float* __restrict__ bias, const float* __restrict__ res,
             void* __restrict__ Cv, int ldc, int K) {
    extern __shared__ __half smh[];
    __half* As = smh;                        // 3 stages of 128 x AS_LD
    __half* Bs = smh + 3 * ASTG;             // 3 stages of 32  x BS_LD
    float*  wb = (float*)(Bs + 3 * BSTG);    // 8 warps x 16 x 20

    int tid  = threadIdx.x;
    int warp = tid >> 5, lane = tid & 31;
    int wm = warp >> 2;                      // 0..1 -> 64-row slab
    int wn = warp & 3;                       // 0..3 -> 32-col slab
    int m0 = blockIdx.y * 128;
    int n0 = blockIdx.x * 128;

    wmma::fragment<wmma::accumulator, 16, 16, 16, float> acc[4][2];
    #pragma unroll
    for (int i = 0; i < 4; i++)
        #pragma unroll
        for (int j = 0; j < 2; j++) wmma::fill_fragment(acc[i][j], 0.f);

    const int KT = K >> 5;

    stage_load(As, Bs, A, lda, W, ldb, m0, n0, 0, tid);
    __pipeline_commit();
    stage_load(As + ASTG, Bs + BSTG, A, lda, W, ldb, m0, n0, 32, tid);
    __pipeline_commit();

    for (int kt = 0; kt < KT; kt++) {
        __pipeline_wait_prior(1);            // stage kt arrived
        __syncthreads();                     // all warps done with stage kt-1
        if (kt + 2 < KT) {
            int st = (kt + 2) % 3;
            stage_load(As + st * ASTG, Bs + st * BSTG, A, lda, W, ldb,
                       m0, n0, (kt + 2) << 5, tid);
        }
        __pipeline_commit();

        int cur = kt % 3;
        const __half* Ac = As + cur * ASTG + wm * 64 * AS_LD;
        const __half* Bc = Bs + cur * BSTG + wn * 32;
        #pragma unroll
        for (int ks = 0; ks < 2; ks++) {
            wmma::fragment<wmma::matrix_b, 16, 16, 16, __half, wmma::row_major> bf[2];
            #pragma unroll
            for (int j = 0; j < 2; j++)
                wmma::load_matrix_sync(bf[j], Bc + ks * 16 * BS_LD + j * 16, BS_LD);
            #pragma unroll
            for (int i = 0; i < 4; i++) {
                wmma::fragment<wmma::matrix_a, 16, 16, 16, __half, wmma::row_major> af;
                wmma::load_matrix_sync(af, Ac + i * 16 * AS_LD + ks * 16, AS_LD);
                wmma::mma_sync(acc[i][0], af, bf[0], acc[i][0]);
                wmma::mma_sync(acc[i][1], af, bf[1], acc[i][1]);
            }
        }
    }
    __syncthreads();

    // ------------------------------ epilogue --------------------------------
    int er = lane >> 1, ec = (lane & 1) << 3;
    float* wwb = wb + warp * 16 * 20;
    #pragma unroll
    for (int i = 0; i < 4; i++) {
        int gm   = m0 + wm * 64 + i * 16 + er;
        int orow = (MODE == 1) ? tok_map(gm) : gm;
        size_t rowbase = (size_t)orow * ldc;
        #pragma unroll
        for (int j = 0; j < 2; j++) {
            wmma::store_matrix_sync(wwb, acc[i][j], 20, wmma::mem_row_major);
            __syncwarp();
            int gn = n0 + wn * 32 + j * 16 + ec;
            const float* src = wwb + er * 20 + ec;
            float4 v0 = *(const float4*)(src);
            float4 v1 = *(const float4*)(src + 4);
            float4 b0 = *(const float4*)&bias[gn];
            float4 b1 = *(const float4*)&bias[gn + 4];
            float o[8] = {v0.x + b0.x, v0.y + b0.y, v0.z + b0.z, v0.w + b0.w,
                          v1.x + b1.x, v1.y + b1.y, v1.z + b1.z, v1.w + b1.w};
            if (MODE == 2) {
                #pragma unroll
                for (int e = 0; e < 8; e++)
                    o[e] = 0.5f * o[e] * (1.f + erff(o[e] * 0.70710678118654752f));
            }
            if (MODE == 0 || MODE == 2) {
                __half* Ch = (__half*)Cv;
                __half2* dst = (__half2*)&Ch[rowbase + gn];
                dst[0] = __floats2half2_rn(o[0], o[1]);
                dst[1] = __floats2half2_rn(o[2], o[3]);
                dst[2] = __floats2half2_rn(o[4], o[5]);
                dst[3] = __floats2half2_rn(o[6], o[7]);
            } else {
                float4 r0 = *(const float4*)&res[rowbase + gn];
                float4 r1 = *(const float4*)&res[rowbase + gn + 4];
                o[0] += r0.x; o[1] += r0.y; o[2] += r0.z; o[3] += r0.w;
                o[4] += r1.x; o[5] += r1.y; o[6] += r1.z; o[7] += r1.w;
                float* Cf = (float*)Cv;
                *(float4*)&Cf[rowbase + gn]     = make_float4(o[0], o[1], o[2], o[3]);
                *(float4*)&Cf[rowbase + gn + 4] = make_float4(o[4], o[5], o[6], o[7]);
            }
            __syncwarp();
        }
    }
}

// ------------- attention: one block per (window, head), half tiles ----------
__global__ void __launch_bounds__(256)
attn_kernel(const __half* __restrict__ qkv, __half* __restrict__ out) {
    int blk  = blockIdx.x;
    int gw   = blk >> 3;
    int head = blk & 7;
    int w    = gw & 63;
    int tid  = threadIdx.x;

    __shared__ uint4 qs[NTOK][5], ks[NTOK][5], vs[NTOK][5];   // 32 halves/row, pad
    __shared__ float ps[NTOK][52];
    __shared__ int   lab[NTOK];

    if (tid < NTOK) {
        int r = (w >> 3) * 7 + tid / 7;
        int c = (w & 7) * 7 + tid % 7;
        int rr = (r < 49) ? 0 : ((r < 53) ? 1 : 2);
        int cr = (c < 49) ? 0 : ((c < 53) ? 1 : 2);
        lab[tid] = rr * 3 + cr;
    }
    const __half* base = qkv + (size_t)gw * NTOK * 768 + head * 32;
    for (int idx = tid; idx < NTOK * 4; idx += 256) {
        int n = idx >> 2, i = idx & 3;
        const uint4* b4 = (const uint4*)(base + n * 768);
        qs[n][i] = b4[i];
        ks[n][i] = b4[32 + i];      // +256 halves
        vs[n][i] = b4[64 + i];      // +512 halves
    }
    __syncthreads();

    // QK^T with 2x2 register tiles
    for (int idx = tid; idx < 625; idx += 256) {
        int n0 = (idx / 25) << 1, m0 = (idx % 25) << 1;
        int n1 = (n0 + 1 < NTOK) ? n0 + 1 : n0;
        int m1 = (m0 + 1 < NTOK) ? m0 + 1 : m0;
        float s00 = 0.f, s01 = 0.f, s10 = 0.f, s11 = 0.f;
        #pragma unroll
        for (int i = 0; i < 4; i++) {
            float a0[8], a1[8], b0[8], b1[8];
            cvt8(a0, qs[n0][i]); cvt8(a1, qs[n1][i]);
            cvt8(b0, ks[m0][i]); cvt8(b1, ks[m1][i]);
            #pragma unroll
            for (int e = 0; e < 8; e++) {
                s00 = fmaf(a0[e], b0[e], s00);
                s01 = fmaf(a0[e], b1[e], s01);
                s10 = fmaf(a1[e], b0[e], s10);
                s11 = fmaf(a1[e], b1[e], s11);
            }
        }
        int l0 = lab[n0], l1 = lab[n1];
        ps[n0][m0] = s00 * QSCALE + ((l0 == lab[m0]) ? 0.f : -100.f);
        if (m0 + 1 < NTOK)
            ps[n0][m1] = s01 * QSCALE + ((l0 == lab[m1]) ? 0.f : -100.f);
        if (n0 + 1 < NTOK) {
            ps[n1][m0] = s10 * QSCALE + ((l1 == lab[m0]) ? 0.f : -100.f);
            if (m0 + 1 < NTOK)
                ps[n1][m1] = s11 * QSCALE + ((l1 == lab[m1]) ? 0.f : -100.f);
        }
    }
    __syncthreads();

    int lane = tid & 31, warp = tid >> 5;
    for (int n = warp; n < NTOK; n += 8) {
        float s0 = (lane      < NTOK) ? ps[n][lane]      : -1e30f;
        float s1 = (lane + 32 < NTOK) ? ps[n][lane + 32] : -1e30f;
        float mx = fmaxf(s0, s1);
        #pragma unroll
        for (int o = 16; o > 0; o >>= 1) mx = fmaxf(mx, __shfl_xor_sync(0xffffffffu, mx, o));
        float e0 = (lane      < NTOK) ? __expf(s0 - mx) : 0.f;
        float e1 = (lane + 32 < NTOK) ? __expf(s1 - mx) : 0.f;
        float sm = e0 + e1;
        #pragma unroll
        for (int o = 16; o > 0; o >>= 1) sm += __shfl_xor_sync(0xffffffffu, sm, o);
        float inv = 1.f / sm;
        if (lane      < NTOK) ps[n][lane]      = e0 * inv;
        if (lane + 32 < NTOK) ps[n][lane + 32] = e1 * inv;
    }
    __syncthreads();

    // A@V: 2 rows x 8 cols per thread (v loads reused across the row pair)
    for (int idx = tid; idx < 200; idx += 256) {
        int ng = idx >> 3, i = idx & 7;      // ng 0..24, i = half of a uint4 pair
        int n0 = ng << 1;
        int n1 = (n0 + 1 < NTOK) ? n0 + 1 : n0;
        int iq = i >> 1, ih = (i & 1) << 2;  // uint4 index, 4-float half
        float a0[4] = {0.f, 0.f, 0.f, 0.f};
        float a1[4] = {0.f, 0.f, 0.f, 0.f};
        #pragma unroll 7
        for (int m = 0; m < NTOK; m++) {
            float p0 = ps[n0][m], p1 = ps[n1][m];
            float vf[8];
            cvt8(vf, vs[m][iq]);
            #pragma unroll
            for (int e = 0; e < 4; e++) {
                a0[e] = fmaf(p0, vf[ih + e], a0[e]);
                a1[e] = fmaf(p1, vf[ih + e], a1[e]);
            }
        }
        __half2 h0[2], h1[2];
        h0[0] = __floats2half2_rn(a0[0], a0[1]);
        h0[1] = __floats2half2_rn(a0[2], a0[3]);
        h1[0] = __floats2half2_rn(a1[0], a1[1]);
        h1[1] = __floats2half2_rn(a1[2], a1[3]);
        size_t ob = (size_t)gw * NTOK * CC + head * 32 + iq * 8 + ih;
        *(uint2*)&out[ob + (size_t)n0 * CC] = *(uint2*)h0;
        if (n0 + 1 < NTOK)
            *(uint2*)&out[ob + (size_t)n1 * CC] = *(uint2*)h1;
    }
}

// --------------------------------- launch -----------------------------------
extern "C" void kernel_launch(void* const* d_in, const int* in_sizes, int n_in,
                              void* d_out, int out_size) {
    const float* x   = (const float*)d_in[0];
    const float* ag  = (const float*)d_in[1];
    const float* n1w = (const float*)d_in[2];
    const float* n1b = (const float*)d_in[3];
    const float* qw  = (const float*)d_in[4];
    const float* qb  = (const float*)d_in[5];
    const float* kw  = (const float*)d_in[6];
    const float* kb  = (const float*)d_in[7];
    const float* vw  = (const float*)d_in[8];
    const float* vb  = (const float*)d_in[9];
    const float* pw  = (const float*)d_in[10];
    const float* pb  = (const float*)d_in[11];
    const float* n2w = (const float*)d_in[12];
    const float* n2b = (const float*)d_in[13];
    const float* f1w = (const float*)d_in[14];
    const float* f1b = (const float*)d_in[15];
    const float* f2w = (const float*)d_in[16];
    const float* f2b = (const float*)d_in[17];
    float* out = (float*)d_out;

    __half *p_wqk, *p_wv, *p_wp, *p_wf1, *p_wf2, *p_win, *p_qkv, *p_att, *p_ln2, *p_hid;
    float  *p_bc, *p_y1;
    cudaGetSymbolAddress((void**)&p_wqk, g_Wqk);
    cudaGetSymbolAddress((void**)&p_wv,  g_Wv);
    cudaGetSymbolAddress((void**)&p_bc,  g_bc);
    cudaGetSymbolAddress((void**)&p_wp,  g_Wp);
    cudaGetSymbolAddress((void**)&p_wf1, g_Wf1);
    cudaGetSymbolAddress((void**)&p_wf2, g_Wf2);
    cudaGetSymbolAddress((void**)&p_win, g_win);
    cudaGetSymbolAddress((void**)&p_qkv, g_qkv);
    cudaGetSymbolAddress((void**)&p_att, g_att);
    cudaGetSymbolAddress((void**)&p_y1,  g_y1);
    cudaGetSymbolAddress((void**)&p_ln2, g_ln2);
    cudaGetSymbolAddress((void**)&p_hid, g_hid);

    cudaFuncSetAttribute(wgemm_kernel<0>, cudaFuncAttributeMaxDynamicSharedMemorySize, SMEM_SZ);
    cudaFuncSetAttribute(wgemm_kernel<1>, cudaFuncAttributeMaxDynamicSharedMemorySize, SMEM_SZ);
    cudaFuncSetAttribute(wgemm_kernel<2>, cudaFuncAttributeMaxDynamicSharedMemorySize, SMEM_SZ);
    cudaFuncSetAttribute(wgemm_kernel<3>, cudaFuncAttributeMaxDynamicSharedMemorySize, SMEM_SZ);

    const int MT = TOK / 128;   // 784 M-tiles

    build_w_kernel<<<(CGDIM * CGDIM + 255) / 256, 256>>>(qw, qb, kw, kb, vw, vb);
    round_w_kernel<<<(CC * MLPH + 255) / 256, 256>>>(pw, f1w, f2w);
    prep_kernel<<<TOK / 8, 256>>>(x, ag, n1w, n1b);
    // q,k : [TOK,512] @ [512,512] -> qkv cols 0..511 (half out)
    wgemm_kernel<0><<<dim3(4, MT), 256, SMEM_SZ>>>(p_win, CGDIM, p_wqk, CGDIM,
                                                   p_bc, nullptr, p_qkv, 768, 512);
    // v   : [TOK,256] @ [256,256] -> qkv cols 512..767
    wgemm_kernel<0><<<dim3(2, MT), 256, SMEM_SZ>>>(p_win, CGDIM, p_wv, CC,
                                                   p_bc + 512, nullptr, p_qkv + 512, 768, 256);
    attn_kernel<<<(TOK / NTOK) * NHEADS, 256>>>(p_qkv, p_att);
    wgemm_kernel<1><<<dim3(2, MT), 256, SMEM_SZ>>>(p_att, CC, p_wp, CC,
                                                   pb, x, p_y1, CC, 256);
    ln_kernel<<<TOK / 8, 256>>>(p_y1, n2w, n2b, p_ln2);
    wgemm_kernel<2><<<dim3(8, MT), 256, SMEM_SZ>>>(p_ln2, CC, p_wf1, MLPH,
                                                   f1b, nullptr, p_hid, MLPH, 256);
    wgemm_kernel<3><<<dim3(2, MT), 256, SMEM_SZ>>>(p_hid, MLPH, p_wf2, CC,
                                                   f2b, p_y1, out, CC, 1024);
}

// round 14
// speedup vs baseline: 1.3771x; 1.0258x over previous
#include <cuda_runtime.h>
#include <cuda_pipeline.h>
#include <cuda_fp16.h>
#include <mma.h>
#include <math.h>
#include <stdint.h>

using namespace nvcuda;

// ---------------------------------------------------------------------------
// SwinTransformerBlock  (B=32, H=W=56, C=256, G=256, WIN=7, SHIFT=3, HEADS=8)
// Round 13: R10 pipeline (best) with 4-stage cp.async GEMM mainloop.
// ---------------------------------------------------------------------------

#define BB      32
#define HH      56
#define CC      256
#define GG      256
#define CGDIM   512
#define NHEADS  8
#define NTOK    49
#define TOK     (BB*HH*HH)
#define MLPH    1024
#define QSCALE  0.17677669529663687f
#define EPSV    1e-5f

#define AS_LD   40
#define BS_LD   136
#define ASTG    (128*AS_LD)
#define BSTG    (32*BS_LD)
#define NSTG    4
#define SMEM_SZ ((NSTG*ASTG + NSTG*BSTG)*2 + 8*16*20*4)

// ------------------------- scratch (device globals) ------------------------
__device__ __half g_Wqk[CGDIM*CGDIM];        // [K=512][N=512] q|k
__device__ __half g_Wv [CC*CC];              // [K=256][N=256] v
__device__ float  g_bc [768];
__device__ __half g_Wp [CC*CC];
__device__ __half g_Wf1[CC*MLPH];
__device__ __half g_Wf2[MLPH*CC];
__device__ __half g_win[(size_t)TOK*CGDIM];
__device__ __half g_qkv[(size_t)TOK*768];
__device__ __half g_att[(size_t)TOK*CC];
__device__ float  g_y1 [(size_t)TOK*CC];
__device__ __half g_ln2[(size_t)TOK*CC];
__device__ __half g_hid[(size_t)TOK*MLPH];

__device__ __forceinline__ int tok_map(int t) {
    int gw = t / NTOK;
    int n  = t - gw * NTOK;
    int b  = gw >> 6;
    int w  = gw & 63;
    int r  = (w >> 3) * 7 + n / 7;
    int c  = (w & 7) * 7 + n % 7;
    int sr = r + 3; if (sr >= HH) sr -= HH;
    int sc = c + 3; if (sc >= HH) sc -= HH;
    return (b * HH + sr) * HH + sc;
}

__device__ __forceinline__ void cvt8(float* f, uint4 u) {
    __half2* h = (__half2*)&u;
    float2 t;
    t = __half22float2(h[0]); f[0] = t.x; f[1] = t.y;
    t = __half22float2(h[1]); f[2] = t.x; f[3] = t.y;
    t = __half22float2(h[2]); f[4] = t.x; f[5] = t.y;
    t = __half22float2(h[3]); f[6] = t.x; f[7] = t.y;
}

// ------------------- kernel 0: build qk / v weights + biases ----------------
__global__ void build_w_kernel(const float* __restrict__ qw, const float* __restrict__ qb,
                               const float* __restrict__ kw, const float* __restrict__ kb,
                               const float* __restrict__ vw, const float* __restrict__ vb) {
    int i = blockIdx.x * blockDim.x + threadIdx.x;
    if (i < CGDIM * CGDIM) {
        int k = i >> 9, n = i & 511;
        g_Wqk[i] = __float2half_rn((n < 256) ? qw[k * 256 + n] : kw[k * 256 + (n - 256)]);
    }
    if (i < CC * CC) {
        int k = i >> 8, n = i & 255;
        g_Wv[i] = __float2half_rn(vw[k * 256 + n]);
    }
    if (i < 768)
        g_bc[i] = (i < 256) ? qb[i] : ((i < 512) ? kb[i - 256] : vb[i - 512]);
}

// -------------------- convert proj / fc1 / fc2 weights to half --------------
__global__ void round_w_kernel(const float* __restrict__ pw,
                               const float* __restrict__ f1w,
                               const float* __restrict__ f2w) {
    int i = blockIdx.x * blockDim.x + threadIdx.x;
    if (i < CC*CC)   g_Wp[i]  = __float2half_rn(pw[i]);
    if (i < CC*MLPH) { g_Wf1[i] = __float2half_rn(f1w[i]); g_Wf2[i] = __float2half_rn(f2w[i]); }
}

// ------ kernel 1: LN1 + roll + window partition + concat (warp per row) -----
__global__ void __launch_bounds__(256)
prep_kernel(const float* __restrict__ x, const float* __restrict__ guid,
            const float* __restrict__ w, const float* __restrict__ b) {
    int warp = threadIdx.x >> 5, lane = threadIdx.x & 31;
    int row = blockIdx.x * 8 + warp;          // window-major token
    int src = tok_map(row);
    int c0  = lane * 8;
    const float* xr = x + (size_t)src * CC;
    float4 v0 = *(const float4*)(xr + c0);
    float4 v1 = *(const float4*)(xr + c0 + 4);
    float sum = v0.x + v0.y + v0.z + v0.w + v1.x + v1.y + v1.z + v1.w;
    float sq  = v0.x*v0.x + v0.y*v0.y + v0.z*v0.z + v0.w*v0.w
              + v1.x*v1.x + v1.y*v1.y + v1.z*v1.z + v1.w*v1.w;
    #pragma unroll
    for (int o = 16; o > 0; o >>= 1) {
        sum += __shfl_xor_sync(0xffffffffu, sum, o);
        sq  += __shfl_xor_sync(0xffffffffu, sq,  o);
    }
    float mu = sum * (1.f / CC);
    float rs = rsqrtf(sq * (1.f / CC) - mu * mu + EPSV);
    float4 w0 = *(const float4*)(w + c0), w1 = *(const float4*)(w + c0 + 4);
    float4 b0 = *(const float4*)(b + c0), b1 = *(const float4*)(b + c0 + 4);
    __half2 h[4];
    h[0] = __floats2half2_rn((v0.x-mu)*rs*w0.x+b0.x, (v0.y-mu)*rs*w0.y+b0.y);
    h[1] = __floats2half2_rn((v0.z-mu)*rs*w0.z+b0.z, (v0.w-mu)*rs*w0.w+b0.w);
    h[2] = __floats2half2_rn((v1.x-mu)*rs*w1.x+b1.x, (v1.y-mu)*rs*w1.y+b1.y);
    h[3] = __floats2half2_rn((v1.z-mu)*rs*w1.z+b1.z, (v1.w-mu)*rs*w1.w+b1.w);
    *(uint4*)&g_win[(size_t)row * CGDIM + c0] = *(uint4*)h;
    const float* gr = guid + (size_t)src * GG;
    float4 g0 = *(const float4*)(gr + c0), g1 = *(const float4*)(gr + c0 + 4);
    h[0] = __floats2half2_rn(g0.x, g0.y);
    h[1] = __floats2half2_rn(g0.z, g0.w);
    h[2] = __floats2half2_rn(g1.x, g1.y);
    h[3] = __floats2half2_rn(g1.z, g1.w);
    *(uint4*)&g_win[(size_t)row * CGDIM + CC + c0] = *(uint4*)h;
}

// --------------------- LayerNorm (warp per row, half out) -------------------
__global__ void __launch_bounds__(256)
ln_kernel(const float* __restrict__ in, const float* __restrict__ w,
          const float* __restrict__ b, __half* __restrict__ out) {
    int warp = threadIdx.x >> 5, lane = threadIdx.x & 31;
    int row = blockIdx.x * 8 + warp;
    int c0  = lane * 8;
    const float* xr = in + (size_t)row * CC;
    float4 v0 = *(const float4*)(xr + c0);
    float4 v1 = *(const float4*)(xr + c0 + 4);
    float sum = v0.x + v0.y + v0.z + v0.w + v1.x + v1.y + v1.z + v1.w;
    float sq  = v0.x*v0.x + v0.y*v0.y + v0.z*v0.z + v0.w*v0.w
              + v1.x*v1.x + v1.y*v1.y + v1.z*v1.z + v1.w*v1.w;
    #pragma unroll
    for (int o = 16; o > 0; o >>= 1) {
        sum += __shfl_xor_sync(0xffffffffu, sum, o);
        sq  += __shfl_xor_sync(0xffffffffu, sq,  o);
    }
    float mu = sum * (1.f / CC);
    float rs = rsqrtf(sq * (1.f / CC) - mu * mu + EPSV);
    float4 w0 = *(const float4*)(w + c0), w1 = *(const float4*)(w + c0 + 4);
    float4 b0 = *(const float4*)(b + c0), b1 = *(const float4*)(b + c0 + 4);
    __half2 h[4];
    h[0] = __floats2half2_rn((v0.x-mu)*rs*w0.x+b0.x, (v0.y-mu)*rs*w0.y+b0.y);
    h[1] = __floats2half2_rn((v0.z-mu)*rs*w0.z+b0.z, (v0.w-mu)*rs*w0.w+b0.w);
    h[2] = __floats2half2_rn((v1.x-mu)*rs*w1.x+b1.x, (v1.y-mu)*rs*w1.y+b1.y);
    h[3] = __floats2half2_rn((v1.z-mu)*rs*w1.z+b1.z, (v1.w-mu)*rs*w1.w+b1.w);
    *(uint4*)&out[(size_t)row * CC + c0] = *(uint4*)h;
}

// ------------------ stage loader: 128x32 A + 32x128 B (half) ----------------
__device__ __forceinline__ void stage_load(__half* Asd, __half* Bsd,
                                           const __half* __restrict__ A, int lda,
                                           const __half* __restrict__ W, int ldb,
                                           int m0, int n0, int k0, int tid) {
    #pragma unroll
    for (int r = 0; r < 2; r++) {
        int id  = tid + r * 256;
        int row = id >> 2, kq = (id & 3) << 3;     // 128 rows x 32 halves
        __pipeline_memcpy_async(Asd + row * AS_LD + kq,
                                A + (size_t)(m0 + row) * lda + k0 + kq, 16);
    }
    #pragma unroll
    for (int r = 0; r < 2; r++) {
        int id   = tid + r * 256;
        int krow = id >> 4, nq = (id & 15) << 3;   // 32 rows x 128 halves
        __pipeline_memcpy_async(Bsd + krow * BS_LD + nq,
                                W + (size_t)(k0 + krow) * ldb + n0 + nq, 16);
    }
}

// --- fp16 WMMA GEMM: 128x128x32 CTA, 8 warps, 64x32/warp tile, 2 CTA/SM -----
// MODE 0: C(half)  = A@W + bias                  (qkv)
// MODE 1: C(float)[map(m)] = res[map(m)] + A@W + bias   (proj+reverse+residual)
// MODE 2: C(half)  = gelu(A@W + bias)            (fc1)
// MODE 3: C(float) = res + A@W + bias            (fc2+residual)
template <int MODE>
__global__ void __launch_bounds__(256, 2)
wgemm_kernel(const __half* __restrict__ A, int lda,
             const __half* __restrict__ W, int ldb,
             const float* __restrict__ bias, const float* __restrict__ res,
             void* __restrict__ Cv, int ldc, int K) {
    extern __shared__ __half smh[];
    __half* As = smh;                        // NSTG stages of 128 x AS_LD
    __half* Bs = smh + NSTG * ASTG;          // NSTG stages of 32  x BS_LD
    float*  wb = (float*)(Bs + NSTG * BSTG); // 8 warps x 16 x 20

    int tid  = threadIdx.x;
    int warp = tid >> 5, lane = tid & 31;
    int wm = warp >> 2;                      // 0..1 -> 64-row slab
    int wn = warp & 3;                       // 0..3 -> 32-col slab
    int m0 = blockIdx.y * 128;
    int n0 = blockIdx.x * 128;

    wmma::fragment<wmma::accumulator, 16, 16, 16, float> acc[4][2];
    #pragma unroll
    for (int i = 0; i < 4; i++)
        #pragma unroll
        for (int j = 0; j < 2; j++) wmma::fill_fragment(acc[i][j], 0.f);

    const int KT = K >> 5;

    // prefetch 3 stages ahead
    #pragma unroll
    for (int s = 0; s < 3; s++) {
        if (s < KT)
            stage_load(As + s * ASTG, Bs + s * BSTG, A, lda, W, ldb, m0, n0, s << 5, tid);
        __pipeline_commit();
    }

    for (int kt = 0; kt < KT; kt++) {
        __pipeline_wait_prior(2);            // stage kt arrived
        __syncthreads();                     // all warps done with stage kt-1
        if (kt + 3 < KT) {
            int st = (kt + 3) & (NSTG - 1);
            stage_load(As + st * ASTG, Bs + st * BSTG, A, lda, W, ldb,
                       m0, n0, (kt + 3) << 5, tid);
        }
        __pipeline_commit();

        int cur = kt & (NSTG - 1);
        const __half* Ac = As + cur * ASTG + wm * 64 * AS_LD;
        const __half* Bc = Bs + cur * BSTG + wn * 32;
        #pragma unroll
        for (int ks = 0; ks < 2; ks++) {
            wmma::fragment<wmma::matrix_b, 16, 16, 16, __half, wmma::row_major> bf[2];
            #pragma unroll
            for (int j = 0; j < 2; j++)
                wmma::load_matrix_sync(bf[j], Bc + ks * 16 * BS_LD + j * 16, BS_LD);
            #pragma unroll
            for (int i = 0; i < 4; i++) {
                wmma::fragment<wmma::matrix_a, 16, 16, 16, __half, wmma::row_major> af;
                wmma::load_matrix_sync(af, Ac + i * 16 * AS_LD + ks * 16, AS_LD);
                wmma::mma_sync(acc[i][0], af, bf[0], acc[i][0]);
                wmma::mma_sync(acc[i][1], af, bf[1], acc[i][1]);
            }
        }
    }
    __syncthreads();

    // ------------------------------ epilogue --------------------------------
    int er = lane >> 1, ec = (lane & 1) << 3;
    float* wwb = wb + warp * 16 * 20;
    #pragma unroll
    for (int i = 0; i < 4; i++) {
        int gm   = m0 + wm * 64 + i * 16 + er;
        int orow = (MODE == 1) ? tok_map(gm) : gm;
        size_t rowbase = (size_t)orow * ldc;
        #pragma unroll
        for (int j = 0; j < 2; j++) {
            wmma::store_matrix_sync(wwb, acc[i][j], 20, wmma::mem_row_major);
            __syncwarp();
            int gn = n0 + wn * 32 + j * 16 + ec;
            const float* src = wwb + er * 20 + ec;
            float4 v0 = *(const float4*)(src);
            float4 v1 = *(const float4*)(src + 4);
            float4 b0 = *(const float4*)&bias[gn];
            float4 b1 = *(const float4*)&bias[gn + 4];
            float o[8] = {v0.x + b0.x, v0.y + b0.y, v0.z + b0.z, v0.w + b0.w,
                          v1.x + b1.x, v1.y + b1.y, v1.z + b1.z, v1.w + b1.w};
            if (MODE == 2) {
                #pragma unroll
                for (int e = 0; e < 8; e++)
                    o[e] = 0.5f * o[e] * (1.f + erff(o[e] * 0.70710678118654752f));
            }
            if (MODE == 0 || MODE == 2) {
                __half* Ch = (__half*)Cv;
                __half2* dst = (__half2*)&Ch[rowbase + gn];
                dst[0] = __floats2half2_rn(o[0], o[1]);
                dst[1] = __floats2half2_rn(o[2], o[3]);
                dst[2] = __floats2half2_rn(o[4], o[5]);
                dst[3] = __floats2half2_rn(o[6], o[7]);
            } else {
                float4 r0 = *(const float4*)&res[rowbase + gn];
                float4 r1 = *(const float4*)&res[rowbase + gn + 4];
                o[0] += r0.x; o[1] += r0.y; o[2] += r0.z; o[3] += r0.w;
                o[4] += r1.x; o[5] += r1.y; o[6] += r1.z; o[7] += r1.w;
                float* Cf = (float*)Cv;
                *(float4*)&Cf[rowbase + gn]     = make_float4(o[0], o[1], o[2], o[3]);
                *(float4*)&Cf[rowbase + gn + 4] = make_float4(o[4], o[5], o[6], o[7]);
            }
            __syncwarp();
        }
    }
}

// ------------- attention: one block per (window, head), half tiles ----------
__global__ void __launch_bounds__(256)
attn_kernel(const __half* __restrict__ qkv, __half* __restrict__ out) {
    int blk  = blockIdx.x;
    int gw   = blk >> 3;
    int head = blk & 7;
    int w    = gw & 63;
    int tid  = threadIdx.x;

    __shared__ uint4 qs[NTOK][5], ks[NTOK][5], vs[NTOK][5];   // 32 halves/row, pad
    __shared__ float ps[NTOK][52];
    __shared__ int   lab[NTOK];

    if (tid < NTOK) {
        int r = (w >> 3) * 7 + tid / 7;
        int c = (w & 7) * 7 + tid % 7;
        int rr = (r < 49) ? 0 : ((r < 53) ? 1 : 2);
        int cr = (c < 49) ? 0 : ((c < 53) ? 1 : 2);
        lab[tid] = rr * 3 + cr;
    }
    const __half* base = qkv + (size_t)gw * NTOK * 768 + head * 32;
    for (int idx = tid; idx < NTOK * 4; idx += 256) {
        int n = idx >> 2, i = idx & 3;
        const uint4* b4 = (const uint4*)(base + n * 768);
        qs[n][i] = b4[i];
        ks[n][i] = b4[32 + i];      // +256 halves
        vs[n][i] = b4[64 + i];      // +512 halves
    }
    __syncthreads();

    // QK^T with 2x2 register tiles
    for (int idx = tid; idx < 625; idx += 256) {
        int n0 = (idx / 25) << 1, m0 = (idx % 25) << 1;
        int n1 = (n0 + 1 < NTOK) ? n0 + 1 : n0;
        int m1 = (m0 + 1 < NTOK) ? m0 + 1 : m0;
        float s00 = 0.f, s01 = 0.f, s10 = 0.f, s11 = 0.f;
        #pragma unroll
        for (int i = 0; i < 4; i++) {
            float a0[8], a1[8], b0[8], b1[8];
            cvt8(a0, qs[n0][i]); cvt8(a1, qs[n1][i]);
            cvt8(b0, ks[m0][i]); cvt8(b1, ks[m1][i]);
            #pragma unroll
            for (int e = 0; e < 8; e++) {
                s00 = fmaf(a0[e], b0[e], s00);
                s01 = fmaf(a0[e], b1[e], s01);
                s10 = fmaf(a1[e], b0[e], s10);
                s11 = fmaf(a1[e], b1[e], s11);
            }
        }
        int l0 = lab[n0], l1 = lab[n1];
        ps[n0][m0] = s00 * QSCALE + ((l0 == lab[m0]) ? 0.f : -100.f);
        if (m0 + 1 < NTOK)
            ps[n0][m1] = s01 * QSCALE + ((l0 == lab[m1]) ? 0.f : -100.f);
        if (n0 + 1 < NTOK) {
            ps[n1][m0] = s10 * QSCALE + ((l1 == lab[m0]) ? 0.f : -100.f);
            if (m0 + 1 < NTOK)
                ps[n1][m1] = s11 * QSCALE + ((l1 == lab[m1]) ? 0.f : -100.f);
        }
    }
    __syncthreads();

    int lane = tid & 31, warp = tid >> 5;
    for (int n = warp; n < NTOK; n += 8) {
        float s0 = (lane      < NTOK) ? ps[n][lane]      : -1e30f;
        float s1 = (lane + 32 < NTOK) ? ps[n][lane + 32] : -1e30f;
        float mx = fmaxf(s0, s1);
        #pragma unroll
        for (int o = 16; o > 0; o >>= 1) mx = fmaxf(mx, __shfl_xor_sync(0xffffffffu, mx, o));
        float e0 = (lane      < NTOK) ? __expf(s0 - mx) : 0.f;
        float e1 = (lane + 32 < NTOK) ? __expf(s1 - mx) : 0.f;
        float sm = e0 + e1;
        #pragma unroll
        for (int o = 16; o > 0; o >>= 1) sm += __shfl_xor_sync(0xffffffffu, sm, o);
        float inv = 1.f / sm;
        if (lane      < NTOK) ps[n][lane]      = e0 * inv;
        if (lane + 32 < NTOK) ps[n][lane + 32] = e1 * inv;
    }
    __syncthreads();

    // A@V: each thread -> (row n, 8-wide slice of head dim)
    for (int idx = tid; idx < NTOK * 4; idx += 256) {
        int n = idx >> 2, i = idx & 3;
        float a[8] = {0.f, 0.f, 0.f, 0.f, 0.f, 0.f, 0.f, 0.f};
        #pragma unroll 7
        for (int m = 0; m < NTOK; m++) {
            float p = ps[n][m];
            float vf[8];
            cvt8(vf, vs[m][i]);
            #pragma unroll
            for (int e = 0; e < 8; e++) a[e] = fmaf(p, vf[e], a[e]);
        }
        __half2 h[4];
        h[0] = __floats2half2_rn(a[0], a[1]);
        h[1] = __floats2half2_rn(a[2], a[3]);
        h[2] = __floats2half2_rn(a[4], a[5]);
        h[3] = __floats2half2_rn(a[6], a[7]);
        *(uint4*)&out[((size_t)gw * NTOK + n) * CC + head * 32 + i * 8] = *(uint4*)h;
    }
}

// --------------------------------- launch -----------------------------------
extern "C" void kernel_launch(void* const* d_in, const int* in_sizes, int n_in,
                              void* d_out, int out_size) {
    const float* x   = (const float*)d_in[0];
    const float* ag  = (const float*)d_in[1];
    const float* n1w = (const float*)d_in[2];
    const float* n1b = (const float*)d_in[3];
    const float* qw  = (const float*)d_in[4];
    const float* qb  = (const float*)d_in[5];
    const float* kw  = (const float*)d_in[6];
    const float* kb  = (const float*)d_in[7];
    const float* vw  = (const float*)d_in[8];
    const float* vb  = (const float*)d_in[9];
    const float* pw  = (const float*)d_in[10];
    const float* pb  = (const float*)d_in[11];
    const float* n2w = (const float*)d_in[12];
    const float* n2b = (const float*)d_in[13];
    const float* f1w = (const float*)d_in[14];
    const float* f1b = (const float*)d_in[15];
    const float* f2w = (const float*)d_in[16];
    const float* f2b = (const float*)d_in[17];
    float* out = (float*)d_out;

    __half *p_wqk, *p_wv, *p_wp, *p_wf1, *p_wf2, *p_win, *p_qkv, *p_att, *p_ln2, *p_hid;
    float  *p_bc, *p_y1;
    cudaGetSymbolAddress((void**)&p_wqk, g_Wqk);
    cudaGetSymbolAddress((void**)&p_wv,  g_Wv);
    cudaGetSymbolAddress((void**)&p_bc,  g_bc);
    cudaGetSymbolAddress((void**)&p_wp,  g_Wp);
    cudaGetSymbolAddress((void**)&p_wf1, g_Wf1);
    cudaGetSymbolAddress((void**)&p_wf2, g_Wf2);
    cudaGetSymbolAddress((void**)&p_win, g_win);
    cudaGetSymbolAddress((void**)&p_qkv, g_qkv);
    cudaGetSymbolAddress((void**)&p_att, g_att);
    cudaGetSymbolAddress((void**)&p_y1,  g_y1);
    cudaGetSymbolAddress((void**)&p_ln2, g_ln2);
    cudaGetSymbolAddress((void**)&p_hid, g_hid);

    cudaFuncSetAttribute(wgemm_kernel<0>, cudaFuncAttributeMaxDynamicSharedMemorySize, SMEM_SZ);
    cudaFuncSetAttribute(wgemm_kernel<1>, cudaFuncAttributeMaxDynamicSharedMemorySize, SMEM_SZ);
    cudaFuncSetAttribute(wgemm_kernel<2>, cudaFuncAttributeMaxDynamicSharedMemorySize, SMEM_SZ);
    cudaFuncSetAttribute(wgemm_kernel<3>, cudaFuncAttributeMaxDynamicSharedMemorySize, SMEM_SZ);

    const int MT = TOK / 128;   // 784 M-tiles

    build_w_kernel<<<(CGDIM * CGDIM + 255) / 256, 256>>>(qw, qb, kw, kb, vw, vb);
    round_w_kernel<<<(CC * MLPH + 255) / 256, 256>>>(pw, f1w, f2w);
    prep_kernel<<<TOK / 8, 256>>>(x, ag, n1w, n1b);
    // q,k : [TOK,512] @ [512,512] -> qkv cols 0..511 (half out)
    wgemm_kernel<0><<<dim3(4, MT), 256, SMEM_SZ>>>(p_win, CGDIM, p_wqk, CGDIM,
                                                   p_bc, nullptr, p_qkv, 768, 512);
    // v   : [TOK,256] @ [256,256] -> qkv cols 512..767
    wgemm_kernel<0><<<dim3(2, MT), 256, SMEM_SZ>>>(p_win, CGDIM, p_wv, CC,
                                                   p_bc + 512, nullptr, p_qkv + 512, 768, 256);
    attn_kernel<<<(TOK / NTOK) * NHEADS, 256>>>(p_qkv, p_att);
    wgemm_kernel<1><<<dim3(2, MT), 256, SMEM_SZ>>>(p_att, CC, p_wp, CC,
                                                   pb, x, p_y1, CC, 256);
    ln_kernel<<<TOK / 8, 256>>>(p_y1, n2w, n2b, p_ln2);
    wgemm_kernel<2><<<dim3(8, MT), 256, SMEM_SZ>>>(p_ln2, CC, p_wf1, MLPH,
                                                   f1b, nullptr, p_hid, MLPH, 256);
    wgemm_kernel<3><<<dim3(2, MT), 256, SMEM_SZ>>>(p_hid, MLPH, p_wf2, CC,
                                                   f2b, p_y1, out, CC, 1024);
}

// round 15
// speedup vs baseline: 1.4155x; 1.0279x over previous
#include <cuda_runtime.h>
#include <cuda_pipeline.h>
#include <cuda_fp16.h>
#include <mma.h>
#include <math.h>
#include <stdint.h>

using namespace nvcuda;

// ---------------------------------------------------------------------------
// SwinTransformerBlock  (B=32, H=W=56, C=256, G=256, WIN=7, SHIFT=3, HEADS=8)
// Round 14: 128x128x32 CTA with FOUR warps (64x64 warp tiles), 2 CTAs/SM,
//           4-stage cp.async; attention/LN/prep from the 1246us best.
// ---------------------------------------------------------------------------

#define BB      32
#define HH      56
#define CC      256
#define GG      256
#define CGDIM   512
#define NHEADS  8
#define NTOK    49
#define TOK     (BB*HH*HH)
#define MLPH    1024
#define QSCALE  0.17677669529663687f
#define EPSV    1e-5f

#define AS_LD   40
#define BS_LD   136
#define ASTG    (128*AS_LD)
#define BSTG    (32*BS_LD)
#define NSTG    4
#define SMEM_SZ ((NSTG*ASTG + NSTG*BSTG)*2 + 4*16*20*4)

// ------------------------- scratch (device globals) ------------------------
__device__ __half g_Wqk[CGDIM*CGDIM];        // [K=512][N=512] q|k
__device__ __half g_Wv [CC*CC];              // [K=256][N=256] v
__device__ float  g_bc [768];
__device__ __half g_Wp [CC*CC];
__device__ __half g_Wf1[CC*MLPH];
__device__ __half g_Wf2[MLPH*CC];
__device__ __half g_win[(size_t)TOK*CGDIM];
__device__ __half g_qkv[(size_t)TOK*768];
__device__ __half g_att[(size_t)TOK*CC];
__device__ float  g_y1 [(size_t)TOK*CC];
__device__ __half g_ln2[(size_t)TOK*CC];
__device__ __half g_hid[(size_t)TOK*MLPH];

__device__ __forceinline__ int tok_map(int t) {
    int gw = t / NTOK;
    int n  = t - gw * NTOK;
    int b  = gw >> 6;
    int w  = gw & 63;
    int r  = (w >> 3) * 7 + n / 7;
    int c  = (w & 7) * 7 + n % 7;
    int sr = r + 3; if (sr >= HH) sr -= HH;
    int sc = c + 3; if (sc >= HH) sc -= HH;
    return (b * HH + sr) * HH + sc;
}

__device__ __forceinline__ void cvt8(float* f, uint4 u) {
    __half2* h = (__half2*)&u;
    float2 t;
    t = __half22float2(h[0]); f[0] = t.x; f[1] = t.y;
    t = __half22float2(h[1]); f[2] = t.x; f[3] = t.y;
    t = __half22float2(h[2]); f[4] = t.x; f[5] = t.y;
    t = __half22float2(h[3]); f[6] = t.x; f[7] = t.y;
}

// ------------------- kernel 0: build qk / v weights + biases ----------------
__global__ void build_w_kernel(const float* __restrict__ qw, const float* __restrict__ qb,
                               const float* __restrict__ kw, const float* __restrict__ kb,
                               const float* __restrict__ vw, const float* __restrict__ vb) {
    int i = blockIdx.x * blockDim.x + threadIdx.x;
    if (i < CGDIM * CGDIM) {
        int k = i >> 9, n = i & 511;
        g_Wqk[i] = __float2half_rn((n < 256) ? qw[k * 256 + n] : kw[k * 256 + (n - 256)]);
    }
    if (i < CC * CC) {
        int k = i >> 8, n = i & 255;
        g_Wv[i] = __float2half_rn(vw[k * 256 + n]);
    }
    if (i < 768)
        g_bc[i] = (i < 256) ? qb[i] : ((i < 512) ? kb[i - 256] : vb[i - 512]);
}

// -------------------- convert proj / fc1 / fc2 weights to half --------------
__global__ void round_w_kernel(const float* __restrict__ pw,
                               const float* __restrict__ f1w,
                               const float* __restrict__ f2w) {
    int i = blockIdx.x * blockDim.x + threadIdx.x;
    if (i < CC*CC)   g_Wp[i]  = __float2half_rn(pw[i]);
    if (i < CC*MLPH) { g_Wf1[i] = __float2half_rn(f1w[i]); g_Wf2[i] = __float2half_rn(f2w[i]); }
}

// ------ kernel 1: LN1 + roll + window partition + concat (warp per row) -----
__global__ void __launch_bounds__(256)
prep_kernel(const float* __restrict__ x, const float* __restrict__ guid,
            const float* __restrict__ w, const float* __restrict__ b) {
    int warp = threadIdx.x >> 5, lane = threadIdx.x & 31;
    int row = blockIdx.x * 8 + warp;          // window-major token
    int src = tok_map(row);
    int c0  = lane * 8;
    const float* xr = x + (size_t)src * CC;
    float4 v0 = *(const float4*)(xr + c0);
    float4 v1 = *(const float4*)(xr + c0 + 4);
    float sum = v0.x + v0.y + v0.z + v0.w + v1.x + v1.y + v1.z + v1.w;
    float sq  = v0.x*v0.x + v0.y*v0.y + v0.z*v0.z + v0.w*v0.w
              + v1.x*v1.x + v1.y*v1.y + v1.z*v1.z + v1.w*v1.w;
    #pragma unroll
    for (int o = 16; o > 0; o >>= 1) {
        sum += __shfl_xor_sync(0xffffffffu, sum, o);
        sq  += __shfl_xor_sync(0xffffffffu, sq,  o);
    }
    float mu = sum * (1.f / CC);
    float rs = rsqrtf(sq * (1.f / CC) - mu * mu + EPSV);
    float4 w0 = *(const float4*)(w + c0), w1 = *(const float4*)(w + c0 + 4);
    float4 b0 = *(const float4*)(b + c0), b1 = *(const float4*)(b + c0 + 4);
    __half2 h[4];
    h[0] = __floats2half2_rn((v0.x-mu)*rs*w0.x+b0.x, (v0.y-mu)*rs*w0.y+b0.y);
    h[1] = __floats2half2_rn((v0.z-mu)*rs*w0.z+b0.z, (v0.w-mu)*rs*w0.w+b0.w);
    h[2] = __floats2half2_rn((v1.x-mu)*rs*w1.x+b1.x, (v1.y-mu)*rs*w1.y+b1.y);
    h[3] = __floats2half2_rn((v1.z-mu)*rs*w1.z+b1.z, (v1.w-mu)*rs*w1.w+b1.w);
    *(uint4*)&g_win[(size_t)row * CGDIM + c0] = *(uint4*)h;
    const float* gr = guid + (size_t)src * GG;
    float4 g0 = *(const float4*)(gr + c0), g1 = *(const float4*)(gr + c0 + 4);
    h[0] = __floats2half2_rn(g0.x, g0.y);
    h[1] = __floats2half2_rn(g0.z, g0.w);
    h[2] = __floats2half2_rn(g1.x, g1.y);
    h[3] = __floats2half2_rn(g1.z, g1.w);
    *(uint4*)&g_win[(size_t)row * CGDIM + CC + c0] = *(uint4*)h;
}

// --------------------- LayerNorm (warp per row, half out) -------------------
__global__ void __launch_bounds__(256)
ln_kernel(const float* __restrict__ in, const float* __restrict__ w,
          const float* __restrict__ b, __half* __restrict__ out) {
    int warp = threadIdx.x >> 5, lane = threadIdx.x & 31;
    int row = blockIdx.x * 8 + warp;
    int c0  = lane * 8;
    const float* xr = in + (size_t)row * CC;
    float4 v0 = *(const float4*)(xr + c0);
    float4 v1 = *(const float4*)(xr + c0 + 4);
    float sum = v0.x + v0.y + v0.z + v0.w + v1.x + v1.y + v1.z + v1.w;
    float sq  = v0.x*v0.x + v0.y*v0.y + v0.z*v0.z + v0.w*v0.w
              + v1.x*v1.x + v1.y*v1.y + v1.z*v1.z + v1.w*v1.w;
    #pragma unroll
    for (int o = 16; o > 0; o >>= 1) {
        sum += __shfl_xor_sync(0xffffffffu, sum, o);
        sq  += __shfl_xor_sync(0xffffffffu, sq,  o);
    }
    float mu = sum * (1.f / CC);
    float rs = rsqrtf(sq * (1.f / CC) - mu * mu + EPSV);
    float4 w0 = *(const float4*)(w + c0), w1 = *(const float4*)(w + c0 + 4);
    float4 b0 = *(const float4*)(b + c0), b1 = *(const float4*)(b + c0 + 4);
    __half2 h[4];
    h[0] = __floats2half2_rn((v0.x-mu)*rs*w0.x+b0.x, (v0.y-mu)*rs*w0.y+b0.y);
    h[1] = __floats2half2_rn((v0.z-mu)*rs*w0.z+b0.z, (v0.w-mu)*rs*w0.w+b0.w);
    h[2] = __floats2half2_rn((v1.x-mu)*rs*w1.x+b1.x, (v1.y-mu)*rs*w1.y+b1.y);
    h[3] = __floats2half2_rn((v1.z-mu)*rs*w1.z+b1.z, (v1.w-mu)*rs*w1.w+b1.w);
    *(uint4*)&out[(size_t)row * CC + c0] = *(uint4*)h;
}

// ---------- stage loader (128 threads): 128x32 A + 32x128 B (half) ----------
__device__ __forceinline__ void stage_load(__half* Asd, __half* Bsd,
                                           const __half* __restrict__ A, int lda,
                                           const __half* __restrict__ W, int ldb,
                                           int m0, int n0, int k0, int tid) {
    #pragma unroll
    for (int r = 0; r < 4; r++) {
        int id  = tid + r * 128;
        int row = id >> 2, kq = (id & 3) << 3;     // 128 rows x 32 halves
        __pipeline_memcpy_async(Asd + row * AS_LD + kq,
                                A + (size_t)(m0 + row) * lda + k0 + kq, 16);
    }
    #pragma unroll
    for (int r = 0; r < 4; r++) {
        int id   = tid + r * 128;
        int krow = id >> 4, nq = (id & 15) << 3;   // 32 rows x 128 halves
        __pipeline_memcpy_async(Bsd + krow * BS_LD + nq,
                                W + (size_t)(k0 + krow) * ldb + n0 + nq, 16);
    }
}

// -- fp16 WMMA GEMM: 128x128x32 CTA, 4 warps, 64x64/warp tile, 2 CTA/SM ------
// MODE 0: C(half)  = A@W + bias                  (qkv)
// MODE 1: C(float)[map(m)] = res[map(m)] + A@W + bias   (proj+reverse+residual)
// MODE 2: C(half)  = gelu(A@W + bias)            (fc1)
// MODE 3: C(float) = res + A@W + bias            (fc2+residual)
template <int MODE>
__global__ void __launch_bounds__(128, 2)
wgemm_kernel(const __half* __restrict__ A, int lda,
             const __half* __restrict__ W, int ldb,
             const float* __restrict__ bias, const float* __restrict__ res,
             void* __restrict__ Cv, int ldc, int K) {
    extern __shared__ __half smh[];
    __half* As = smh;                        // NSTG stages of 128 x AS_LD
    __half* Bs = smh + NSTG * ASTG;          // NSTG stages of 32  x BS_LD
    float*  wb = (float*)(Bs + NSTG * BSTG); // 4 warps x 16 x 20

    int tid  = threadIdx.x;
    int warp = tid >> 5, lane = tid & 31;
    int wm = warp >> 1;                      // 0..1 -> 64-row slab
    int wn = warp & 1;                       // 0..1 -> 64-col slab
    int m0 = blockIdx.y * 128;
    int n0 = blockIdx.x * 128;

    wmma::fragment<wmma::accumulator, 16, 16, 16, float> acc[4][4];
    #pragma unroll
    for (int i = 0; i < 4; i++)
        #pragma unroll
        for (int j = 0; j < 4; j++) wmma::fill_fragment(acc[i][j], 0.f);

    const int KT = K >> 5;

    // prefetch 3 stages ahead
    #pragma unroll
    for (int s = 0; s < 3; s++) {
        if (s < KT)
            stage_load(As + s * ASTG, Bs + s * BSTG, A, lda, W, ldb, m0, n0, s << 5, tid);
        __pipeline_commit();
    }

    for (int kt = 0; kt < KT; kt++) {
        __pipeline_wait_prior(2);            // stage kt arrived
        __syncthreads();                     // all warps done with stage kt-1
        if (kt + 3 < KT) {
            int st = (kt + 3) & (NSTG - 1);
            stage_load(As + st * ASTG, Bs + st * BSTG, A, lda, W, ldb,
                       m0, n0, (kt + 3) << 5, tid);
        }
        __pipeline_commit();

        int cur = kt & (NSTG - 1);
        const __half* Ac = As + cur * ASTG + wm * 64 * AS_LD;
        const __half* Bc = Bs + cur * BSTG + wn * 64;
        #pragma unroll
        for (int ks = 0; ks < 2; ks++) {
            wmma::fragment<wmma::matrix_b, 16, 16, 16, __half, wmma::row_major> bf[4];
            #pragma unroll
            for (int j = 0; j < 4; j++)
                wmma::load_matrix_sync(bf[j], Bc + ks * 16 * BS_LD + j * 16, BS_LD);
            #pragma unroll
            for (int i = 0; i < 4; i++) {
                wmma::fragment<wmma::matrix_a, 16, 16, 16, __half, wmma::row_major> af;
                wmma::load_matrix_sync(af, Ac + i * 16 * AS_LD + ks * 16, AS_LD);
                #pragma unroll
                for (int j = 0; j < 4; j++)
                    wmma::mma_sync(acc[i][j], af, bf[j], acc[i][j]);
            }
        }
    }
    __syncthreads();

    // ------------------------------ epilogue --------------------------------
    int er = lane >> 1, ec = (lane & 1) << 3;
    float* wwb = wb + warp * 16 * 20;
    #pragma unroll
    for (int i = 0; i < 4; i++) {
        int gm   = m0 + wm * 64 + i * 16 + er;
        int orow = (MODE == 1) ? tok_map(gm) : gm;
        size_t rowbase = (size_t)orow * ldc;
        #pragma unroll
        for (int j = 0; j < 4; j++) {
            wmma::store_matrix_sync(wwb, acc[i][j], 20, wmma::mem_row_major);
            __syncwarp();
            int gn = n0 + wn * 64 + j * 16 + ec;
            const float* src = wwb + er * 20 + ec;
            float4 v0 = *(const float4*)(src);
            float4 v1 = *(const float4*)(src + 4);
            float4 b0 = *(const float4*)&bias[gn];
            float4 b1 = *(const float4*)&bias[gn + 4];
            float o[8] = {v0.x + b0.x, v0.y + b0.y, v0.z + b0.z, v0.w + b0.w,
                          v1.x + b1.x, v1.y + b1.y, v1.z + b1.z, v1.w + b1.w};
            if (MODE == 2) {
                #pragma unroll
                for (int e = 0; e < 8; e++)
                    o[e] = 0.5f * o[e] * (1.f + erff(o[e] * 0.70710678118654752f));
            }
            if (MODE == 0 || MODE == 2) {
                __half* Ch = (__half*)Cv;
                __half2* dst = (__half2*)&Ch[rowbase + gn];
                dst[0] = __floats2half2_rn(o[0], o[1]);
                dst[1] = __floats2half2_rn(o[2], o[3]);
                dst[2] = __floats2half2_rn(o[4], o[5]);
                dst[3] = __floats2half2_rn(o[6], o[7]);
            } else {
                float4 r0 = *(const float4*)&res[rowbase + gn];
                float4 r1 = *(const float4*)&res[rowbase + gn + 4];
                o[0] += r0.x; o[1] += r0.y; o[2] += r0.z; o[3] += r0.w;
                o[4] += r1.x; o[5] += r1.y; o[6] += r1.z; o[7] += r1.w;
                float* Cf = (float*)Cv;
                *(float4*)&Cf[rowbase + gn]     = make_float4(o[0], o[1], o[2], o[3]);
                *(float4*)&Cf[rowbase + gn + 4] = make_float4(o[4], o[5], o[6], o[7]);
            }
            __syncwarp();
        }
    }
}

// ------------- attention: one block per (window, head), half tiles ----------
__global__ void __launch_bounds__(256)
attn_kernel(const __half* __restrict__ qkv, __half* __restrict__ out) {
    int blk  = blockIdx.x;
    int gw   = blk >> 3;
    int head = blk & 7;
    int w    = gw & 63;
    int tid  = threadIdx.x;

    __shared__ uint4 qs[NTOK][5], ks[NTOK][5], vs[NTOK][5];   // 32 halves/row, pad
    __shared__ float ps[NTOK][52];
    __shared__ int   lab[NTOK];

    if (tid < NTOK) {
        int r = (w >> 3) * 7 + tid / 7;
        int c = (w & 7) * 7 + tid % 7;
        int rr = (r < 49) ? 0 : ((r < 53) ? 1 : 2);
        int cr = (c < 49) ? 0 : ((c < 53) ? 1 : 2);
        lab[tid] = rr * 3 + cr;
    }
    const __half* base = qkv + (size_t)gw * NTOK * 768 + head * 32;
    for (int idx = tid; idx < NTOK * 4; idx += 256) {
        int n = idx >> 2, i = idx & 3;
        const uint4* b4 = (const uint4*)(base + n * 768);
        qs[n][i] = b4[i];
        ks[n][i] = b4[32 + i];      // +256 halves
        vs[n][i] = b4[64 + i];      // +512 halves
    }
    __syncthreads();

    // QK^T with 2x2 register tiles
    for (int idx = tid; idx < 625; idx += 256) {
        int n0 = (idx / 25) << 1, m0 = (idx % 25) << 1;
        int n1 = (n0 + 1 < NTOK) ? n0 + 1 : n0;
        int m1 = (m0 + 1 < NTOK) ? m0 + 1 : m0;
        float s00 = 0.f, s01 = 0.f, s10 = 0.f, s11 = 0.f;
        #pragma unroll
        for (int i = 0; i < 4; i++) {
            float a0[8], a1[8], b0[8], b1[8];
            cvt8(a0, qs[n0][i]); cvt8(a1, qs[n1][i]);
            cvt8(b0, ks[m0][i]); cvt8(b1, ks[m1][i]);
            #pragma unroll
            for (int e = 0; e < 8; e++) {
                s00 = fmaf(a0[e], b0[e], s00);
                s01 = fmaf(a0[e], b1[e], s01);
                s10 = fmaf(a1[e], b0[e], s10);
                s11 = fmaf(a1[e], b1[e], s11);
            }
        }
        int l0 = lab[n0], l1 = lab[n1];
        ps[n0][m0] = s00 * QSCALE + ((l0 == lab[m0]) ? 0.f : -100.f);
        if (m0 + 1 < NTOK)
            ps[n0][m1] = s01 * QSCALE + ((l0 == lab[m1]) ? 0.f : -100.f);
        if (n0 + 1 < NTOK) {
            ps[n1][m0] = s10 * QSCALE + ((l1 == lab[m0]) ? 0.f : -100.f);
            if (m0 + 1 < NTOK)
                ps[n1][m1] = s11 * QSCALE + ((l1 == lab[m1]) ? 0.f : -100.f);
        }
    }
    __syncthreads();

    int lane = tid & 31, warp = tid >> 5;
    for (int n = warp; n < NTOK; n += 8) {
        float s0 = (lane      < NTOK) ? ps[n][lane]      : -1e30f;
        float s1 = (lane + 32 < NTOK) ? ps[n][lane + 32] : -1e30f;
        float mx = fmaxf(s0, s1);
        #pragma unroll
        for (int o = 16; o > 0; o >>= 1) mx = fmaxf(mx, __shfl_xor_sync(0xffffffffu, mx, o));
        float e0 = (lane      < NTOK) ? __expf(s0 - mx) : 0.f;
        float e1 = (lane + 32 < NTOK) ? __expf(s1 - mx) : 0.f;
        float sm = e0 + e1;
        #pragma unroll
        for (int o = 16; o > 0; o >>= 1) sm += __shfl_xor_sync(0xffffffffu, sm, o);
        float inv = 1.f / sm;
        if (lane      < NTOK) ps[n][lane]      = e0 * inv;
        if (lane + 32 < NTOK) ps[n][lane + 32] = e1 * inv;
    }
    __syncthreads();

    // A@V: each thread -> (row n, 8-wide slice of head dim)
    for (int idx = tid; idx < NTOK * 4; idx += 256) {
        int n = idx >> 2, i = idx & 3;
        float a[8] = {0.f, 0.f, 0.f, 0.f, 0.f, 0.f, 0.f, 0.f};
        #pragma unroll 7
        for (int m = 0; m < NTOK; m++) {
            float p = ps[n][m];
            float vf[8];
            cvt8(vf, vs[m][i]);
            #pragma unroll
            for (int e = 0; e < 8; e++) a[e] = fmaf(p, vf[e], a[e]);
        }
        __half2 h[4];
        h[0] = __floats2half2_rn(a[0], a[1]);
        h[1] = __floats2half2_rn(a[2], a[3]);
        h[2] = __floats2half2_rn(a[4], a[5]);
        h[3] = __floats2half2_rn(a[6], a[7]);
        *(uint4*)&out[((size_t)gw * NTOK + n) * CC + head * 32 + i * 8] = *(uint4*)h;
    }
}

// --------------------------------- launch -----------------------------------
extern "C" void kernel_launch(void* const* d_in, const int* in_sizes, int n_in,
                              void* d_out, int out_size) {
    const float* x   = (const float*)d_in[0];
    const float* ag  = (const float*)d_in[1];
    const float* n1w = (const float*)d_in[2];
    const float* n1b = (const float*)d_in[3];
    const float* qw  = (const float*)d_in[4];
    const float* qb  = (const float*)d_in[5];
    const float* kw  = (const float*)d_in[6];
    const float* kb  = (const float*)d_in[7];
    const float* vw  = (const float*)d_in[8];
    const float* vb  = (const float*)d_in[9];
    const float* pw  = (const float*)d_in[10];
    const float* pb  = (const float*)d_in[11];
    const float* n2w = (const float*)d_in[12];
    const float* n2b = (const float*)d_in[13];
    const float* f1w = (const float*)d_in[14];
    const float* f1b = (const float*)d_in[15];
    const float* f2w = (const float*)d_in[16];
    const float* f2b = (const float*)d_in[17];
    float* out = (float*)d_out;

    __half *p_wqk, *p_wv, *p_wp, *p_wf1, *p_wf2, *p_win, *p_qkv, *p_att, *p_ln2, *p_hid;
    float  *p_bc, *p_y1;
    cudaGetSymbolAddress((void**)&p_wqk, g_Wqk);
    cudaGetSymbolAddress((void**)&p_wv,  g_Wv);
    cudaGetSymbolAddress((void**)&p_bc,  g_bc);
    cudaGetSymbolAddress((void**)&p_wp,  g_Wp);
    cudaGetSymbolAddress((void**)&p_wf1, g_Wf1);
    cudaGetSymbolAddress((void**)&p_wf2, g_Wf2);
    cudaGetSymbolAddress((void**)&p_win, g_win);
    cudaGetSymbolAddress((void**)&p_qkv, g_qkv);
    cudaGetSymbolAddress((void**)&p_att, g_att);
    cudaGetSymbolAddress((void**)&p_y1,  g_y1);
    cudaGetSymbolAddress((void**)&p_ln2, g_ln2);
    cudaGetSymbolAddress((void**)&p_hid, g_hid);

    cudaFuncSetAttribute(wgemm_kernel<0>, cudaFuncAttributeMaxDynamicSharedMemorySize, SMEM_SZ);
    cudaFuncSetAttribute(wgemm_kernel<1>, cudaFuncAttributeMaxDynamicSharedMemorySize, SMEM_SZ);
    cudaFuncSetAttribute(wgemm_kernel<2>, cudaFuncAttributeMaxDynamicSharedMemorySize, SMEM_SZ);
    cudaFuncSetAttribute(wgemm_kernel<3>, cudaFuncAttributeMaxDynamicSharedMemorySize, SMEM_SZ);

    const int MT = TOK / 128;   // 784 M-tiles

    build_w_kernel<<<(CGDIM * CGDIM + 255) / 256, 256>>>(qw, qb, kw, kb, vw, vb);
    round_w_kernel<<<(CC * MLPH + 255) / 256, 256>>>(pw, f1w, f2w);
    prep_kernel<<<TOK / 8, 256>>>(x, ag, n1w, n1b);
    // q,k : [TOK,512] @ [512,512] -> qkv cols 0..511 (half out)
    wgemm_kernel<0><<<dim3(4, MT), 128, SMEM_SZ>>>(p_win, CGDIM, p_wqk, CGDIM,
                                                   p_bc, nullptr, p_qkv, 768, 512);
    // v   : [TOK,256] @ [256,256] -> qkv cols 512..767
    wgemm_kernel<0><<<dim3(2, MT), 128, SMEM_SZ>>>(p_win, CGDIM, p_wv, CC,
                                                   p_bc + 512, nullptr, p_qkv + 512, 768, 256);
    attn_kernel<<<(TOK / NTOK) * NHEADS, 256>>>(p_qkv, p_att);
    wgemm_kernel<1><<<dim3(2, MT), 128, SMEM_SZ>>>(p_att, CC, p_wp, CC,
                                                   pb, x, p_y1, CC, 256);
    ln_kernel<<<TOK / 8, 256>>>(p_y1, n2w, n2b, p_ln2);
    wgemm_kernel<2><<<dim3(8, MT), 128, SMEM_SZ>>>(p_ln2, CC, p_wf1, MLPH,
                                                   f1b, nullptr, p_hid, MLPH, 256);
    wgemm_kernel<3><<<dim3(2, MT), 128, SMEM_SZ>>>(p_hid, MLPH, p_wf2, CC,
                                                   f2b, p_y1, out, CC, 1024);
}